// round 14
// baseline (speedup 1.0000x reference)
#include <cuda_runtime.h>
#include <cuda_fp16.h>
#include <math.h>
#include <stdint.h>

#define NN 50000
#define NE 800000
#define D 128
#define NTILES_MAX 391
#define NP (NTILES_MAX * 128)
#define PITCH 136                      // fp16 elems per smem row (conflict-free ldmatrix)
#define SMEM_SZ (3 * 128 * PITCH * 2)  // 3 tiles: A, Wh, Wl  (102 KB)

// ---------------- scratch (no allocation allowed) ----------------
__device__ float g_q[NP * D];
__device__ __half g_kh[NP * D];                   // k (fp16)
__device__ __half g_vh[NP * D];                   // v (fp16)
__device__ __half g_sh[NP * D];                   // struc hi
__device__ __half g_dh[NP * D], g_dl[NP * D];     // delta hi/lo (lo only for ds addend)
__device__ __half g_wh[5 * D * D], g_wl[5 * D * D];
__device__ int   g_hist[NN];
__device__ int   g_off[NN + 1];
__device__ int   g_cur[NN];
__device__ int   g_part[128];
__device__ int   g_sdst[NE];
__device__ float g_sw[NE];

// ---------------- helpers ----------------
__device__ __forceinline__ uint32_t smem_u32(const void* p) {
    uint32_t a;
    asm("{ .reg .u64 t; cvta.to.shared.u64 t, %1; cvt.u32.u64 %0, t; }" : "=r"(a) : "l"(p));
    return a;
}

#define LDM_X4(r0, r1, r2, r3, addr) \
    asm volatile("ldmatrix.sync.aligned.m8n8.x4.shared.b16 {%0,%1,%2,%3}, [%4];" \
                 : "=r"(r0), "=r"(r1), "=r"(r2), "=r"(r3) : "r"(addr))

#define MMA16816(d, a, b) \
    asm volatile("mma.sync.aligned.m16n8k16.row.col.f32.f16.f16.f32 " \
                 "{%0,%1,%2,%3}, {%4,%5,%6,%7}, {%8,%9}, {%0,%1,%2,%3};" \
                 : "+f"((d)[0]), "+f"((d)[1]), "+f"((d)[2]), "+f"((d)[3]) \
                 : "r"((a)[0]), "r"((a)[1]), "r"((a)[2]), "r"((a)[3]), \
                   "r"((b)[0]), "r"((b)[1]))

// split f32 pair -> fp16 hi/lo at even index
__device__ __forceinline__ void store_hl(__half* bh, __half* bl,
                                         size_t idx, float x, float y) {
    __half hx = __float2half_rn(x), hy = __float2half_rn(y);
    float lx = x - __half2float(hx), ly = y - __half2float(hy);
    *(__half2*)(bh + idx) = __halves2half2(hx, hy);
    *(__half2*)(bl + idx) = __halves2half2(__float2half_rn(lx), __float2half_rn(ly));
}

// 2-term hi/lo mainloop over K=128: acc += A*Bh + A*Bl
__device__ __forceinline__ void mainloop2(float acc[2][8][4],
                                          uint32_t aOff, uint32_t bOffH, uint32_t bOffL) {
    const uint32_t aStep = 16 * PITCH * 2;
#pragma unroll
    for (int mi = 0; mi < 2; mi++)
#pragma unroll
        for (int ni = 0; ni < 8; ni++)
#pragma unroll
            for (int j = 0; j < 4; j++) acc[mi][ni][j] = 0.f;

#pragma unroll 2
    for (int s = 0; s < 8; s++) {
        uint32_t ko = s * 32;
        uint32_t a[2][4], bh[8][2], bl[8][2];
        LDM_X4(a[0][0], a[0][1], a[0][2], a[0][3], aOff + ko);
        LDM_X4(a[1][0], a[1][1], a[1][2], a[1][3], aOff + aStep + ko);
#pragma unroll
        for (int nb = 0; nb < 4; nb++) {
            uint32_t t0, t1, t2, t3;
            LDM_X4(t0, t1, t2, t3, bOffH + nb * aStep + ko);
            bh[nb * 2][0] = t0; bh[nb * 2][1] = t1;
            bh[nb * 2 + 1][0] = t2; bh[nb * 2 + 1][1] = t3;
            LDM_X4(t0, t1, t2, t3, bOffL + nb * aStep + ko);
            bl[nb * 2][0] = t0; bl[nb * 2][1] = t1;
            bl[nb * 2 + 1][0] = t2; bl[nb * 2 + 1][1] = t3;
        }
#pragma unroll
        for (int mi = 0; mi < 2; mi++)
#pragma unroll
            for (int ni = 0; ni < 8; ni++) {
                MMA16816(acc[mi][ni], a[mi], bh[ni]);
                MMA16816(acc[mi][ni], a[mi], bl[ni]);
            }
    }
}

// ---------------- LayerNorm + exact GELU + emit (warp per row) ----------------
__device__ __forceinline__ float gelu_exact(float h) {
    return 0.5f * h * (1.0f + erff(h * 0.70710678118654752f));
}

__global__ void ln_gelu_kernel(const float* __restrict__ x,
                               const float* __restrict__ struc,
                               const float* __restrict__ sc,
                               const float* __restrict__ bi, int n, int npad) {
    int warp = threadIdx.x >> 5;
    int lane = threadIdx.x & 31;
    int row = blockIdx.x * 8 + warp;
    if (row >= npad) return;
    int c0 = lane * 4;
    size_t base = (size_t)row * D + c0;

    float4 o = make_float4(0.f, 0.f, 0.f, 0.f);
    float4 sv = make_float4(0.f, 0.f, 0.f, 0.f);
    if (row < n) {
        float4 v = *(const float4*)(x + base);
        sv = *(const float4*)(struc + base);
        float s  = v.x + v.y + v.z + v.w;
        float ss = v.x * v.x + v.y * v.y + v.z * v.z + v.w * v.w;
#pragma unroll
        for (int d = 16; d; d >>= 1) {
            s  += __shfl_xor_sync(0xffffffffu, s, d);
            ss += __shfl_xor_sync(0xffffffffu, ss, d);
        }
        float mean = s * (1.0f / D);
        float var  = ss * (1.0f / D) - mean * mean;
        float rstd = rsqrtf(var + 1e-5f);
        float4 scv = *(const float4*)(sc + c0);
        float4 biv = *(const float4*)(bi + c0);
        o.x = gelu_exact((v.x - mean) * rstd * scv.x + biv.x);
        o.y = gelu_exact((v.y - mean) * rstd * scv.y + biv.y);
        o.z = gelu_exact((v.z - mean) * rstd * scv.z + biv.z);
        o.w = gelu_exact((v.w - mean) * rstd * scv.w + biv.w);
    }
    store_hl(g_dh, g_dl, base,     o.x, o.y);
    store_hl(g_dh, g_dl, base + 2, o.z, o.w);
    *(__half2*)(g_sh + base)     = __halves2half2(__float2half_rn(sv.x), __float2half_rn(sv.y));
    *(__half2*)(g_sh + base + 2) = __halves2half2(__float2half_rn(sv.z), __float2half_rn(sv.w));
}

// ---------------- weight split (5 x 128x128) ----------------
__global__ void conv_w_kernel(const float* __restrict__ W0, const float* __restrict__ W1,
                              const float* __restrict__ W2, const float* __restrict__ W3,
                              const float* __restrict__ W4) {
    int widx = blockIdx.x;
    const float* W = widx == 0 ? W0 : widx == 1 ? W1 : widx == 2 ? W2 : widx == 3 ? W3 : W4;
    __half* bh = g_wh + (size_t)widx * D * D;
    __half* bl = g_wl + (size_t)widx * D * D;
    for (int p = threadIdx.x; p < D * D / 2; p += blockDim.x) {
        size_t i = (size_t)p * 2;
        store_hl(bh, bl, i, W[i], W[i + 1]);
    }
}

// ---------------- generic 2-term mma GEMM: CTA = 128m x 128n x 128k ----------------
__global__ void __launch_bounds__(256) mma_gemm(
    const __half* __restrict__ Ah, int widx,
    const float* __restrict__ bias, const float* __restrict__ addend,
    float* __restrict__ outF, __half* __restrict__ outHalf, int Mreal, float alpha)
{
    extern __shared__ char smem_raw[];
    __half* sA  = (__half*)smem_raw;
    __half* sWh = sA + 128 * PITCH;
    __half* sWl = sWh + 128 * PITCH;
    int tid = threadIdx.x, wid = tid >> 5, lane = tid & 31;
    size_t tile = blockIdx.x;

    {
        const float4* gA  = (const float4*)(Ah + tile * 128 * D);
        const float4* gWh = (const float4*)(g_wh + (size_t)widx * D * D);
        const float4* gWl = (const float4*)(g_wl + (size_t)widx * D * D);
        for (int idx = tid; idx < 128 * 16; idx += 256) {
            int r = idx >> 4, c8 = (idx & 15) * 8;
            *(float4*)(sA  + r * PITCH + c8) = gA[idx];
            *(float4*)(sWh + r * PITCH + c8) = gWh[idx];
            *(float4*)(sWl + r * PITCH + c8) = gWl[idx];
        }
    }
    __syncthreads();

    int m0 = (wid & 3) * 32;
    int n0w = (wid >> 2) * 64;
    int aRow = ((lane >> 3) & 1) * 8 + (lane & 7);
    int aCol = (lane >> 4) * 8;
    uint32_t aOff = smem_u32(sA) + ((m0 + aRow) * PITCH + aCol) * 2;
    int bRow = (lane >> 4) * 8 + (lane & 7);
    int bCol = ((lane >> 3) & 1) * 8;
    uint32_t bOffH = smem_u32(sWh) + ((n0w + bRow) * PITCH + bCol) * 2;
    uint32_t bOffL = smem_u32(sWl) + ((n0w + bRow) * PITCH + bCol) * 2;

    float acc[2][8][4];
    mainloop2(acc, aOff, bOffH, bOffL);

    int r = lane >> 2, c2 = (lane & 3) * 2;
#pragma unroll
    for (int mi = 0; mi < 2; mi++) {
#pragma unroll
        for (int half = 0; half < 2; half++) {
            int grow = (int)tile * 128 + m0 + mi * 16 + half * 8 + r;
            if (grow >= Mreal) continue;
#pragma unroll
            for (int ni = 0; ni < 8; ni++) {
                int col = n0w + ni * 8 + c2;
                float o0 = acc[mi][ni][half * 2 + 0];
                float o1 = acc[mi][ni][half * 2 + 1];
                if (bias) { o0 += bias[col]; o1 += bias[col + 1]; }
                o0 *= alpha; o1 *= alpha;
                size_t idx = (size_t)grow * D + col;
                if (addend) {
                    float2 ad = *(const float2*)(addend + idx);
                    o0 += ad.x; o1 += ad.y;
                }
                if (outF) *(float2*)(outF + idx) = make_float2(o0, o1);
                if (outHalf)
                    *(__half2*)(outHalf + idx) =
                        __halves2half2(__float2half_rn(o0), __float2half_rn(o1));
            }
        }
    }
}

// ---------------- fused ds + q + k: ds stays in smem (all 2-term) ----------------
__global__ void __launch_bounds__(256) mma_fused_dsqk(
    const float* __restrict__ bs, const float* __restrict__ bq,
    const float* __restrict__ bk, int Nreal)
{
    extern __shared__ char smem_raw[];
    __half* sA  = (__half*)smem_raw;
    __half* sWh = sA + 128 * PITCH;
    __half* sWl = sWh + 128 * PITCH;
    int tid = threadIdx.x, wid = tid >> 5, lane = tid & 31;
    size_t tile = blockIdx.x;

    // stage A: load struc hi + Ws hi/lo
    {
        const float4* gA  = (const float4*)(g_sh + tile * 128 * D);
        const float4* gWh = (const float4*)(g_wh);
        const float4* gWl = (const float4*)(g_wl);
        for (int idx = tid; idx < 128 * 16; idx += 256) {
            int r = idx >> 4, c8 = (idx & 15) * 8;
            *(float4*)(sA  + r * PITCH + c8) = gA[idx];
            *(float4*)(sWh + r * PITCH + c8) = gWh[idx];
            *(float4*)(sWl + r * PITCH + c8) = gWl[idx];
        }
    }
    __syncthreads();

    int m0 = (wid & 3) * 32;
    int n0w = (wid >> 2) * 64;
    int aRow = ((lane >> 3) & 1) * 8 + (lane & 7);
    int aCol = (lane >> 4) * 8;
    uint32_t aOff = smem_u32(sA) + ((m0 + aRow) * PITCH + aCol) * 2;
    int bRow = (lane >> 4) * 8 + (lane & 7);
    int bCol = ((lane >> 3) & 1) * 8;
    uint32_t bOffH = smem_u32(sWh) + ((n0w + bRow) * PITCH + bCol) * 2;
    uint32_t bOffL = smem_u32(sWl) + ((n0w + bRow) * PITCH + bCol) * 2;

    float acc[2][8][4];
    mainloop2(acc, aOff, bOffH, bOffL);              // struc @ Ws
    __syncthreads();

    // ds epilogue -> overwrite sA with ds (fp16); delta addend from dh+dl; reload Wq
    int r = lane >> 2, c2 = (lane & 3) * 2;
#pragma unroll
    for (int mi = 0; mi < 2; mi++) {
#pragma unroll
        for (int half = 0; half < 2; half++) {
            int lrow = m0 + mi * 16 + half * 8 + r;
            size_t grow = tile * 128 + lrow;
#pragma unroll
            for (int ni = 0; ni < 8; ni++) {
                int col = n0w + ni * 8 + c2;
                size_t idx = grow * D + col;
                float2 dh = __half22float2(*(const __half2*)(g_dh + idx));
                float2 dl = __half22float2(*(const __half2*)(g_dl + idx));
                float o0 = acc[mi][ni][half * 2 + 0] + bs[col] + dh.x + dl.x;
                float o1 = acc[mi][ni][half * 2 + 1] + bs[col + 1] + dh.y + dl.y;
                *(__half2*)(sA + (size_t)lrow * PITCH + col) =
                    __halves2half2(__float2half_rn(o0), __float2half_rn(o1));
            }
        }
    }
    {
        const float4* gWh = (const float4*)(g_wh + (size_t)1 * D * D);
        const float4* gWl = (const float4*)(g_wl + (size_t)1 * D * D);
        for (int idx = tid; idx < 128 * 16; idx += 256) {
            int rr = idx >> 4, c8 = (idx & 15) * 8;
            *(float4*)(sWh + rr * PITCH + c8) = gWh[idx];
            *(float4*)(sWl + rr * PITCH + c8) = gWl[idx];
        }
    }
    __syncthreads();

    // stage B: q = (ds @ Wq + bq) * 0.25
    mainloop2(acc, aOff, bOffH, bOffL);
#pragma unroll
    for (int mi = 0; mi < 2; mi++) {
#pragma unroll
        for (int half = 0; half < 2; half++) {
            int grow = (int)tile * 128 + m0 + mi * 16 + half * 8 + r;
            if (grow >= Nreal) continue;
#pragma unroll
            for (int ni = 0; ni < 8; ni++) {
                int col = n0w + ni * 8 + c2;
                float o0 = (acc[mi][ni][half * 2 + 0] + bq[col]) * 0.25f;
                float o1 = (acc[mi][ni][half * 2 + 1] + bq[col + 1]) * 0.25f;
                *(float2*)(g_q + (size_t)grow * D + col) = make_float2(o0, o1);
            }
        }
    }
    __syncthreads();
    {
        const float4* gWh = (const float4*)(g_wh + (size_t)2 * D * D);
        const float4* gWl = (const float4*)(g_wl + (size_t)2 * D * D);
        for (int idx = tid; idx < 128 * 16; idx += 256) {
            int rr = idx >> 4, c8 = (idx & 15) * 8;
            *(float4*)(sWh + rr * PITCH + c8) = gWh[idx];
            *(float4*)(sWl + rr * PITCH + c8) = gWl[idx];
        }
    }
    __syncthreads();

    // stage C: k = ds @ Wk + bk -> fp16
    mainloop2(acc, aOff, bOffH, bOffL);
#pragma unroll
    for (int mi = 0; mi < 2; mi++) {
#pragma unroll
        for (int half = 0; half < 2; half++) {
            int grow = (int)tile * 128 + m0 + mi * 16 + half * 8 + r;
            if (grow >= Nreal) continue;
#pragma unroll
            for (int ni = 0; ni < 8; ni++) {
                int col = n0w + ni * 8 + c2;
                float o0 = acc[mi][ni][half * 2 + 0] + bk[col];
                float o1 = acc[mi][ni][half * 2 + 1] + bk[col + 1];
                *(__half2*)(g_kh + (size_t)grow * D + col) =
                    __halves2half2(__float2half_rn(o0), __float2half_rn(o1));
            }
        }
    }
}

// ---------------- fused agg + out-GEMM: CTA = 128-node tile ----------------
// phase 1: 8 warps aggregate 16 nodes each -> agg rows (fp16) straight into smem A
// phase 2: out = agg @ Wo^T (2-term) + in_feats -> d_out
__global__ void __launch_bounds__(256) mma_agg_out(
    const float* __restrict__ in_feats, float* __restrict__ outF, int Nreal)
{
    extern __shared__ char smem_raw[];
    __half* sA  = (__half*)smem_raw;
    __half* sWh = sA + 128 * PITCH;
    __half* sWl = sWh + 128 * PITCH;
    int tid = threadIdx.x, wid = tid >> 5, lane = tid & 31;
    size_t tile = blockIdx.x;

    // load Wo hi/lo tiles
    {
        const float4* gWh = (const float4*)(g_wh + (size_t)4 * D * D);
        const float4* gWl = (const float4*)(g_wl + (size_t)4 * D * D);
        for (int idx = tid; idx < 128 * 16; idx += 256) {
            int rr = idx >> 4, c8 = (idx & 15) * 8;
            *(float4*)(sWh + rr * PITCH + c8) = gWh[idx];
            *(float4*)(sWl + rr * PITCH + c8) = gWl[idx];
        }
    }

    // phase 1: per-warp edge aggregation, 16 nodes per warp, write fp16 rows to sA
    for (int i = 0; i < 16; i++) {
        int lrow = wid * 16 + i;
        int node = (int)tile * 128 + lrow;
        float4 acc = make_float4(0.f, 0.f, 0.f, 0.f);
        if (node < Nreal) {
            int beg = g_off[node], end = g_off[node + 1];
            float4 q = *(const float4*)&g_q[(size_t)node * D + lane * 4];
            int e = beg;
            for (; e + 1 < end; e += 2) {
                int d0 = g_sdst[e], d1 = g_sdst[e + 1];
                float w0 = g_sw[e], w1 = g_sw[e + 1];
                uint2 kr0 = *(const uint2*)&g_kh[(size_t)d0 * D + lane * 4];
                uint2 kr1 = *(const uint2*)&g_kh[(size_t)d1 * D + lane * 4];
                uint2 vr0 = *(const uint2*)&g_vh[(size_t)d0 * D + lane * 4];
                uint2 vr1 = *(const uint2*)&g_vh[(size_t)d1 * D + lane * 4];
                float2 ka = __half22float2(*(__half2*)&kr0.x), kb = __half22float2(*(__half2*)&kr0.y);
                float2 kc = __half22float2(*(__half2*)&kr1.x), kd = __half22float2(*(__half2*)&kr1.y);
                float p0 = q.x * ka.x + q.y * ka.y + q.z * kb.x + q.w * kb.y;
                float p1 = q.x * kc.x + q.y * kc.y + q.z * kd.x + q.w * kd.y;
                p0 += __shfl_xor_sync(0xffffffffu, p0, 1);
                p0 += __shfl_xor_sync(0xffffffffu, p0, 2);
                p1 += __shfl_xor_sync(0xffffffffu, p1, 1);
                p1 += __shfl_xor_sync(0xffffffffu, p1, 2);
                float a0 = w0 / (1.0f + expf(-p0));
                float a1 = w1 / (1.0f + expf(-p1));
                float2 va = __half22float2(*(__half2*)&vr0.x), vb = __half22float2(*(__half2*)&vr0.y);
                float2 vc = __half22float2(*(__half2*)&vr1.x), vd = __half22float2(*(__half2*)&vr1.y);
                acc.x += a0 * va.x + a1 * vc.x;
                acc.y += a0 * va.y + a1 * vc.y;
                acc.z += a0 * vb.x + a1 * vd.x;
                acc.w += a0 * vb.y + a1 * vd.y;
            }
            if (e < end) {
                int d0 = g_sdst[e];
                float w0 = g_sw[e];
                uint2 kr = *(const uint2*)&g_kh[(size_t)d0 * D + lane * 4];
                float2 k01 = __half22float2(*(__half2*)&kr.x);
                float2 k23 = __half22float2(*(__half2*)&kr.y);
                float p = q.x * k01.x + q.y * k01.y + q.z * k23.x + q.w * k23.y;
                p += __shfl_xor_sync(0xffffffffu, p, 1);
                p += __shfl_xor_sync(0xffffffffu, p, 2);
                float attn = w0 / (1.0f + expf(-p));
                uint2 vr = *(const uint2*)&g_vh[(size_t)d0 * D + lane * 4];
                float2 v01 = __half22float2(*(__half2*)&vr.x);
                float2 v23 = __half22float2(*(__half2*)&vr.y);
                acc.x += attn * v01.x;
                acc.y += attn * v01.y;
                acc.z += attn * v23.x;
                acc.w += attn * v23.y;
            }
        }
        size_t so = (size_t)lrow * PITCH + lane * 4;
        *(__half2*)(sA + so)     = __halves2half2(__float2half_rn(acc.x), __float2half_rn(acc.y));
        *(__half2*)(sA + so + 2) = __halves2half2(__float2half_rn(acc.z), __float2half_rn(acc.w));
    }
    __syncthreads();

    // phase 2: out = agg @ Wo^T + in_feats
    int m0 = (wid & 3) * 32;
    int n0w = (wid >> 2) * 64;
    int aRow = ((lane >> 3) & 1) * 8 + (lane & 7);
    int aCol = (lane >> 4) * 8;
    uint32_t aOff = smem_u32(sA) + ((m0 + aRow) * PITCH + aCol) * 2;
    int bRow = (lane >> 4) * 8 + (lane & 7);
    int bCol = ((lane >> 3) & 1) * 8;
    uint32_t bOffH = smem_u32(sWh) + ((n0w + bRow) * PITCH + bCol) * 2;
    uint32_t bOffL = smem_u32(sWl) + ((n0w + bRow) * PITCH + bCol) * 2;

    float acc2[2][8][4];
    mainloop2(acc2, aOff, bOffH, bOffL);

    int r = lane >> 2, c2 = (lane & 3) * 2;
#pragma unroll
    for (int mi = 0; mi < 2; mi++) {
#pragma unroll
        for (int half = 0; half < 2; half++) {
            int grow = (int)tile * 128 + m0 + mi * 16 + half * 8 + r;
            if (grow >= Nreal) continue;
#pragma unroll
            for (int ni = 0; ni < 8; ni++) {
                int col = n0w + ni * 8 + c2;
                size_t idx = (size_t)grow * D + col;
                float2 ad = *(const float2*)(in_feats + idx);
                float o0 = acc2[mi][ni][half * 2 + 0] + ad.x;
                float o1 = acc2[mi][ni][half * 2 + 1] + ad.y;
                *(float2*)(outF + idx) = make_float2(o0, o1);
            }
        }
    }
}

// ---------------- counting sort of edges by src ----------------
__global__ void hist_kernel(const int* __restrict__ src, int E) {
    int e = blockIdx.x * blockDim.x + threadIdx.x;
    if (e < E) atomicAdd(&g_hist[src[e]], 1);
}

__global__ void scan_part_kernel(int n) {
    __shared__ int wsum[16];
    int b = blockIdx.x, t = threadIdx.x;
    int i = b * 512 + t;
    int v = (i < n) ? g_hist[i] : 0;
    int x = v;
#pragma unroll
    for (int d = 16; d; d >>= 1) x += __shfl_xor_sync(0xffffffffu, x, d);
    if ((t & 31) == 0) wsum[t >> 5] = x;
    __syncthreads();
    if (t < 16) {
        int s = wsum[t];
#pragma unroll
        for (int d = 8; d; d >>= 1) s += __shfl_xor_sync(0xffffu, s, d);
        if (t == 0) g_part[b] = s;
    }
}

__global__ void scan_mid_kernel(int nb) {
    __shared__ int wsum[4];
    int t = threadIdx.x, lane = t & 31, w = t >> 5;
    int v = (t < nb) ? g_part[t] : 0;
    int x = v;
#pragma unroll
    for (int d = 1; d < 32; d <<= 1) {
        int nbv = __shfl_up_sync(0xffffffffu, x, d);
        if (lane >= d) x += nbv;
    }
    if (lane == 31) wsum[w] = x;
    __syncthreads();
    if (t == 0) {
        int c = 0;
        for (int j = 0; j < 4; j++) { int tmp = wsum[j]; wsum[j] = c; c += tmp; }
    }
    __syncthreads();
    if (t < nb) g_part[t] = x - v + wsum[w];
}

__global__ void scan_final_kernel(int n, int E) {
    __shared__ int wsum[16];
    int b = blockIdx.x, t = threadIdx.x, lane = t & 31, w = t >> 5;
    int i = b * 512 + t;
    int v = (i < n) ? g_hist[i] : 0;
    int x = v;
#pragma unroll
    for (int d = 1; d < 32; d <<= 1) {
        int nbv = __shfl_up_sync(0xffffffffu, x, d);
        if (lane >= d) x += nbv;
    }
    if (lane == 31) wsum[w] = x;
    __syncthreads();
    if (t < 16) {
        int s = wsum[t];
#pragma unroll
        for (int d = 1; d < 16; d <<= 1) {
            int nbv = __shfl_up_sync(0xffffu, s, d);
            if ((t & 15) >= d) s += nbv;
        }
        wsum[t] = s;
    }
    __syncthreads();
    int base = g_part[b] + (w ? wsum[w - 1] : 0);
    if (i < n) {
        int excl = base + x - v;
        g_off[i] = excl;
        g_cur[i] = excl;
    }
    if (b == 0 && t == 0) g_off[n] = E;
}

__global__ void scatter_kernel(const int* __restrict__ src, const int* __restrict__ dst,
                               const float* __restrict__ w, int E) {
    int e = blockIdx.x * blockDim.x + threadIdx.x;
    if (e < E) {
        int s = src[e];
        int p = atomicAdd(&g_cur[s], 1);
        g_sdst[p] = dst[e];
        g_sw[p]   = w[e];
    }
}

// ---------------- launch ----------------
extern "C" void kernel_launch(void* const* d_in, const int* in_sizes, int n_in,
                              void* d_out, int out_size) {
    const float* in_feats = (const float*)d_in[0];
    const float* struc    = (const float*)d_in[1];
    const float* ew       = (const float*)d_in[2];
    const float* ln_s     = (const float*)d_in[3];
    const float* ln_b     = (const float*)d_in[4];
    const float* Ws = (const float*)d_in[5];
    const float* bs = (const float*)d_in[6];
    const float* Wq = (const float*)d_in[7];
    const float* bq = (const float*)d_in[8];
    const float* Wk = (const float*)d_in[9];
    const float* bk = (const float*)d_in[10];
    const float* Wv = (const float*)d_in[11];
    const float* bv = (const float*)d_in[12];
    const float* Wo = (const float*)d_in[13];
    const int* eids = (const int*)d_in[14];

    int E = in_sizes[2];
    int N = in_sizes[0] / D;
    int tiles = (N + 127) / 128;
    int npad = tiles * 128;
    const int* src = eids;
    const int* dst = eids + E;

    static cudaStream_t s1 = nullptr, s2 = nullptr;
    static cudaEvent_t e_root = nullptr, e_prep = nullptr, e_w = nullptr,
                       e_v = nullptr, e_edges = nullptr;
    if (!s1) {
        cudaStreamCreateWithFlags(&s1, cudaStreamNonBlocking);
        cudaStreamCreateWithFlags(&s2, cudaStreamNonBlocking);
        cudaEventCreateWithFlags(&e_root,  cudaEventDisableTiming);
        cudaEventCreateWithFlags(&e_prep,  cudaEventDisableTiming);
        cudaEventCreateWithFlags(&e_w,     cudaEventDisableTiming);
        cudaEventCreateWithFlags(&e_v,     cudaEventDisableTiming);
        cudaEventCreateWithFlags(&e_edges, cudaEventDisableTiming);
        cudaFuncSetAttribute((const void*)mma_gemm,
                             cudaFuncAttributeMaxDynamicSharedMemorySize, SMEM_SZ);
        cudaFuncSetAttribute((const void*)mma_fused_dsqk,
                             cudaFuncAttributeMaxDynamicSharedMemorySize, SMEM_SZ);
        cudaFuncSetAttribute((const void*)mma_agg_out,
                             cudaFuncAttributeMaxDynamicSharedMemorySize, SMEM_SZ);
    }

    float* p_q;
    __half *p_kh, *p_vh, *p_dh;
    int* p_hist;
    cudaGetSymbolAddress((void**)&p_q, g_q);
    cudaGetSymbolAddress((void**)&p_kh, g_kh);
    cudaGetSymbolAddress((void**)&p_vh, g_vh);
    cudaGetSymbolAddress((void**)&p_dh, g_dh);
    cudaGetSymbolAddress((void**)&p_hist, g_hist);

    cudaEventRecord(e_root, 0);

    // branch s2: weight split (tiny) then edge counting sort
    cudaStreamWaitEvent(s2, e_root, 0);
    conv_w_kernel<<<5, 256, 0, s2>>>(Ws, Wq, Wk, Wv, Wo);
    cudaEventRecord(e_w, s2);
    int nb = (N + 511) / 512;
    cudaMemsetAsync(p_hist, 0, N * sizeof(int), s2);
    hist_kernel<<<(E + 255) / 256, 256, 0, s2>>>(src, E);
    scan_part_kernel<<<nb, 512, 0, s2>>>(N);
    scan_mid_kernel<<<1, 128, 0, s2>>>(nb);
    scan_final_kernel<<<nb, 512, 0, s2>>>(N, E);
    scatter_kernel<<<(E + 255) / 256, 256, 0, s2>>>(src, dst, ew, E);
    cudaEventRecord(e_edges, s2);

    // main stream: node prep
    ln_gelu_kernel<<<npad / 8, 256>>>(in_feats, struc, ln_s, ln_b, N, npad);
    cudaEventRecord(e_prep, 0);

    // branch s1: v = delta @ Wv^T + bv -> fp16 (overlaps fused dsqk)
    cudaStreamWaitEvent(s1, e_prep, 0);
    cudaStreamWaitEvent(s1, e_w, 0);
    mma_gemm<<<tiles, 256, SMEM_SZ, s1>>>(p_dh, 3, bv, nullptr, nullptr, p_vh, N, 1.0f);
    cudaEventRecord(e_v, s1);

    // main stream: fused ds -> q, k(fp16)
    cudaStreamWaitEvent(0, e_w, 0);
    mma_fused_dsqk<<<tiles, 256, SMEM_SZ>>>(bs, bq, bk, N);

    // join branches, fused aggregate + out-GEMM
    cudaStreamWaitEvent(0, e_v, 0);
    cudaStreamWaitEvent(0, e_edges, 0);
    mma_agg_out<<<tiles, 256, SMEM_SZ>>>(in_feats, (float*)d_out, N);
}

// round 15
// speedup vs baseline: 1.5934x; 1.5934x over previous
#include <cuda_runtime.h>
#include <cuda_fp16.h>
#include <math.h>
#include <stdint.h>

#define NN 50000
#define NE 800000
#define D 128
#define NTILES_MAX 391
#define NP (NTILES_MAX * 128)
#define PITCH 136                      // fp16 elems per smem row (conflict-free ldmatrix)
#define SMEM_SZ (3 * 128 * PITCH * 2)  // 3 tiles: A, Wh, Wl  (102 KB)

// ---------------- scratch (no allocation allowed) ----------------
__device__ float g_q[NP * D];
__device__ __half g_kh[NP * D];                   // k (fp16)
__device__ __half g_vh[NP * D];                   // v (fp16)
__device__ __half g_sh[NP * D];                   // struc hi
__device__ __half g_dh[NP * D], g_dl[NP * D];     // delta hi/lo (lo only for ds addend)
__device__ __half g_agh[NP * D];                  // agg hi (pads stay zero)
__device__ __half g_wh[5 * D * D], g_wl[5 * D * D];
__device__ int   g_hist[NN];
__device__ int   g_off[NN + 1];
__device__ int   g_cur[NN];
__device__ int   g_part[128];
__device__ int   g_sdst[NE];
__device__ float g_sw[NE];

// ---------------- helpers ----------------
__device__ __forceinline__ uint32_t smem_u32(const void* p) {
    uint32_t a;
    asm("{ .reg .u64 t; cvta.to.shared.u64 t, %1; cvt.u32.u64 %0, t; }" : "=r"(a) : "l"(p));
    return a;
}

#define LDM_X4(r0, r1, r2, r3, addr) \
    asm volatile("ldmatrix.sync.aligned.m8n8.x4.shared.b16 {%0,%1,%2,%3}, [%4];" \
                 : "=r"(r0), "=r"(r1), "=r"(r2), "=r"(r3) : "r"(addr))

#define MMA16816(d, a, b) \
    asm volatile("mma.sync.aligned.m16n8k16.row.col.f32.f16.f16.f32 " \
                 "{%0,%1,%2,%3}, {%4,%5,%6,%7}, {%8,%9}, {%0,%1,%2,%3};" \
                 : "+f"((d)[0]), "+f"((d)[1]), "+f"((d)[2]), "+f"((d)[3]) \
                 : "r"((a)[0]), "r"((a)[1]), "r"((a)[2]), "r"((a)[3]), \
                   "r"((b)[0]), "r"((b)[1]))

// split f32 pair -> fp16 hi/lo at even index
__device__ __forceinline__ void store_hl(__half* bh, __half* bl,
                                         size_t idx, float x, float y) {
    __half hx = __float2half_rn(x), hy = __float2half_rn(y);
    float lx = x - __half2float(hx), ly = y - __half2float(hy);
    *(__half2*)(bh + idx) = __halves2half2(hx, hy);
    *(__half2*)(bl + idx) = __halves2half2(__float2half_rn(lx), __float2half_rn(ly));
}

// 2-term hi/lo mainloop over K=128: acc += A*Bh + A*Bl
__device__ __forceinline__ void mainloop2(float acc[2][8][4],
                                          uint32_t aOff, uint32_t bOffH, uint32_t bOffL) {
    const uint32_t aStep = 16 * PITCH * 2;
#pragma unroll
    for (int mi = 0; mi < 2; mi++)
#pragma unroll
        for (int ni = 0; ni < 8; ni++)
#pragma unroll
            for (int j = 0; j < 4; j++) acc[mi][ni][j] = 0.f;

#pragma unroll 2
    for (int s = 0; s < 8; s++) {
        uint32_t ko = s * 32;
        uint32_t a[2][4], bh[8][2], bl[8][2];
        LDM_X4(a[0][0], a[0][1], a[0][2], a[0][3], aOff + ko);
        LDM_X4(a[1][0], a[1][1], a[1][2], a[1][3], aOff + aStep + ko);
#pragma unroll
        for (int nb = 0; nb < 4; nb++) {
            uint32_t t0, t1, t2, t3;
            LDM_X4(t0, t1, t2, t3, bOffH + nb * aStep + ko);
            bh[nb * 2][0] = t0; bh[nb * 2][1] = t1;
            bh[nb * 2 + 1][0] = t2; bh[nb * 2 + 1][1] = t3;
            LDM_X4(t0, t1, t2, t3, bOffL + nb * aStep + ko);
            bl[nb * 2][0] = t0; bl[nb * 2][1] = t1;
            bl[nb * 2 + 1][0] = t2; bl[nb * 2 + 1][1] = t3;
        }
#pragma unroll
        for (int mi = 0; mi < 2; mi++)
#pragma unroll
            for (int ni = 0; ni < 8; ni++) {
                MMA16816(acc[mi][ni], a[mi], bh[ni]);
                MMA16816(acc[mi][ni], a[mi], bl[ni]);
            }
    }
}

// ---------------- LayerNorm + exact GELU + emit (warp per row) ----------------
__device__ __forceinline__ float gelu_exact(float h) {
    return 0.5f * h * (1.0f + erff(h * 0.70710678118654752f));
}

__global__ void ln_gelu_kernel(const float* __restrict__ x,
                               const float* __restrict__ struc,
                               const float* __restrict__ sc,
                               const float* __restrict__ bi, int n, int npad) {
    int warp = threadIdx.x >> 5;
    int lane = threadIdx.x & 31;
    int row = blockIdx.x * 8 + warp;
    if (row >= npad) return;
    int c0 = lane * 4;
    size_t base = (size_t)row * D + c0;

    float4 o = make_float4(0.f, 0.f, 0.f, 0.f);
    float4 sv = make_float4(0.f, 0.f, 0.f, 0.f);
    if (row < n) {
        float4 v = *(const float4*)(x + base);
        sv = *(const float4*)(struc + base);
        float s  = v.x + v.y + v.z + v.w;
        float ss = v.x * v.x + v.y * v.y + v.z * v.z + v.w * v.w;
#pragma unroll
        for (int d = 16; d; d >>= 1) {
            s  += __shfl_xor_sync(0xffffffffu, s, d);
            ss += __shfl_xor_sync(0xffffffffu, ss, d);
        }
        float mean = s * (1.0f / D);
        float var  = ss * (1.0f / D) - mean * mean;
        float rstd = rsqrtf(var + 1e-5f);
        float4 scv = *(const float4*)(sc + c0);
        float4 biv = *(const float4*)(bi + c0);
        o.x = gelu_exact((v.x - mean) * rstd * scv.x + biv.x);
        o.y = gelu_exact((v.y - mean) * rstd * scv.y + biv.y);
        o.z = gelu_exact((v.z - mean) * rstd * scv.z + biv.z);
        o.w = gelu_exact((v.w - mean) * rstd * scv.w + biv.w);
    }
    store_hl(g_dh, g_dl, base,     o.x, o.y);
    store_hl(g_dh, g_dl, base + 2, o.z, o.w);
    *(__half2*)(g_sh + base)     = __halves2half2(__float2half_rn(sv.x), __float2half_rn(sv.y));
    *(__half2*)(g_sh + base + 2) = __halves2half2(__float2half_rn(sv.z), __float2half_rn(sv.w));
}

// ---------------- weight split (5 x 128x128) ----------------
__global__ void conv_w_kernel(const float* __restrict__ W0, const float* __restrict__ W1,
                              const float* __restrict__ W2, const float* __restrict__ W3,
                              const float* __restrict__ W4) {
    int widx = blockIdx.x;
    const float* W = widx == 0 ? W0 : widx == 1 ? W1 : widx == 2 ? W2 : widx == 3 ? W3 : W4;
    __half* bh = g_wh + (size_t)widx * D * D;
    __half* bl = g_wl + (size_t)widx * D * D;
    for (int p = threadIdx.x; p < D * D / 2; p += blockDim.x) {
        size_t i = (size_t)p * 2;
        store_hl(bh, bl, i, W[i], W[i + 1]);
    }
}

// ---------------- generic 2-term mma GEMM: CTA = 128m x 128n x 128k ----------------
__global__ void __launch_bounds__(256) mma_gemm(
    const __half* __restrict__ Ah, int widx,
    const float* __restrict__ bias, const float* __restrict__ addend,
    float* __restrict__ outF, __half* __restrict__ outHalf, int Mreal, float alpha)
{
    extern __shared__ char smem_raw[];
    __half* sA  = (__half*)smem_raw;
    __half* sWh = sA + 128 * PITCH;
    __half* sWl = sWh + 128 * PITCH;
    int tid = threadIdx.x, wid = tid >> 5, lane = tid & 31;
    size_t tile = blockIdx.x;

    {
        const float4* gA  = (const float4*)(Ah + tile * 128 * D);
        const float4* gWh = (const float4*)(g_wh + (size_t)widx * D * D);
        const float4* gWl = (const float4*)(g_wl + (size_t)widx * D * D);
        for (int idx = tid; idx < 128 * 16; idx += 256) {
            int r = idx >> 4, c8 = (idx & 15) * 8;
            *(float4*)(sA  + r * PITCH + c8) = gA[idx];
            *(float4*)(sWh + r * PITCH + c8) = gWh[idx];
            *(float4*)(sWl + r * PITCH + c8) = gWl[idx];
        }
    }
    __syncthreads();

    int m0 = (wid & 3) * 32;
    int n0w = (wid >> 2) * 64;
    int aRow = ((lane >> 3) & 1) * 8 + (lane & 7);
    int aCol = (lane >> 4) * 8;
    uint32_t aOff = smem_u32(sA) + ((m0 + aRow) * PITCH + aCol) * 2;
    int bRow = (lane >> 4) * 8 + (lane & 7);
    int bCol = ((lane >> 3) & 1) * 8;
    uint32_t bOffH = smem_u32(sWh) + ((n0w + bRow) * PITCH + bCol) * 2;
    uint32_t bOffL = smem_u32(sWl) + ((n0w + bRow) * PITCH + bCol) * 2;

    float acc[2][8][4];
    mainloop2(acc, aOff, bOffH, bOffL);

    int r = lane >> 2, c2 = (lane & 3) * 2;
#pragma unroll
    for (int mi = 0; mi < 2; mi++) {
#pragma unroll
        for (int half = 0; half < 2; half++) {
            int grow = (int)tile * 128 + m0 + mi * 16 + half * 8 + r;
            if (grow >= Mreal) continue;
#pragma unroll
            for (int ni = 0; ni < 8; ni++) {
                int col = n0w + ni * 8 + c2;
                float o0 = acc[mi][ni][half * 2 + 0];
                float o1 = acc[mi][ni][half * 2 + 1];
                if (bias) { o0 += bias[col]; o1 += bias[col + 1]; }
                o0 *= alpha; o1 *= alpha;
                size_t idx = (size_t)grow * D + col;
                if (addend) {
                    float2 ad = *(const float2*)(addend + idx);
                    o0 += ad.x; o1 += ad.y;
                }
                if (outF) *(float2*)(outF + idx) = make_float2(o0, o1);
                if (outHalf)
                    *(__half2*)(outHalf + idx) =
                        __halves2half2(__float2half_rn(o0), __float2half_rn(o1));
            }
        }
    }
}

// ---------------- fused ds + q + k: ds stays in smem (all 2-term) ----------------
__global__ void __launch_bounds__(256) mma_fused_dsqk(
    const float* __restrict__ bs, const float* __restrict__ bq,
    const float* __restrict__ bk, int Nreal)
{
    extern __shared__ char smem_raw[];
    __half* sA  = (__half*)smem_raw;
    __half* sWh = sA + 128 * PITCH;
    __half* sWl = sWh + 128 * PITCH;
    int tid = threadIdx.x, wid = tid >> 5, lane = tid & 31;
    size_t tile = blockIdx.x;

    // stage A: load struc hi + Ws hi/lo
    {
        const float4* gA  = (const float4*)(g_sh + tile * 128 * D);
        const float4* gWh = (const float4*)(g_wh);
        const float4* gWl = (const float4*)(g_wl);
        for (int idx = tid; idx < 128 * 16; idx += 256) {
            int r = idx >> 4, c8 = (idx & 15) * 8;
            *(float4*)(sA  + r * PITCH + c8) = gA[idx];
            *(float4*)(sWh + r * PITCH + c8) = gWh[idx];
            *(float4*)(sWl + r * PITCH + c8) = gWl[idx];
        }
    }
    __syncthreads();

    int m0 = (wid & 3) * 32;
    int n0w = (wid >> 2) * 64;
    int aRow = ((lane >> 3) & 1) * 8 + (lane & 7);
    int aCol = (lane >> 4) * 8;
    uint32_t aOff = smem_u32(sA) + ((m0 + aRow) * PITCH + aCol) * 2;
    int bRow = (lane >> 4) * 8 + (lane & 7);
    int bCol = ((lane >> 3) & 1) * 8;
    uint32_t bOffH = smem_u32(sWh) + ((n0w + bRow) * PITCH + bCol) * 2;
    uint32_t bOffL = smem_u32(sWl) + ((n0w + bRow) * PITCH + bCol) * 2;

    float acc[2][8][4];
    mainloop2(acc, aOff, bOffH, bOffL);              // struc @ Ws
    __syncthreads();

    // ds epilogue -> overwrite sA with ds (fp16); delta addend from dh+dl; reload Wq
    int r = lane >> 2, c2 = (lane & 3) * 2;
#pragma unroll
    for (int mi = 0; mi < 2; mi++) {
#pragma unroll
        for (int half = 0; half < 2; half++) {
            int lrow = m0 + mi * 16 + half * 8 + r;
            size_t grow = tile * 128 + lrow;
#pragma unroll
            for (int ni = 0; ni < 8; ni++) {
                int col = n0w + ni * 8 + c2;
                size_t idx = grow * D + col;
                float2 dh = __half22float2(*(const __half2*)(g_dh + idx));
                float2 dl = __half22float2(*(const __half2*)(g_dl + idx));
                float o0 = acc[mi][ni][half * 2 + 0] + bs[col] + dh.x + dl.x;
                float o1 = acc[mi][ni][half * 2 + 1] + bs[col + 1] + dh.y + dl.y;
                *(__half2*)(sA + (size_t)lrow * PITCH + col) =
                    __halves2half2(__float2half_rn(o0), __float2half_rn(o1));
            }
        }
    }
    {
        const float4* gWh = (const float4*)(g_wh + (size_t)1 * D * D);
        const float4* gWl = (const float4*)(g_wl + (size_t)1 * D * D);
        for (int idx = tid; idx < 128 * 16; idx += 256) {
            int rr = idx >> 4, c8 = (idx & 15) * 8;
            *(float4*)(sWh + rr * PITCH + c8) = gWh[idx];
            *(float4*)(sWl + rr * PITCH + c8) = gWl[idx];
        }
    }
    __syncthreads();

    // stage B: q = (ds @ Wq + bq) * 0.25
    mainloop2(acc, aOff, bOffH, bOffL);
#pragma unroll
    for (int mi = 0; mi < 2; mi++) {
#pragma unroll
        for (int half = 0; half < 2; half++) {
            int grow = (int)tile * 128 + m0 + mi * 16 + half * 8 + r;
            if (grow >= Nreal) continue;
#pragma unroll
            for (int ni = 0; ni < 8; ni++) {
                int col = n0w + ni * 8 + c2;
                float o0 = (acc[mi][ni][half * 2 + 0] + bq[col]) * 0.25f;
                float o1 = (acc[mi][ni][half * 2 + 1] + bq[col + 1]) * 0.25f;
                *(float2*)(g_q + (size_t)grow * D + col) = make_float2(o0, o1);
            }
        }
    }
    __syncthreads();
    {
        const float4* gWh = (const float4*)(g_wh + (size_t)2 * D * D);
        const float4* gWl = (const float4*)(g_wl + (size_t)2 * D * D);
        for (int idx = tid; idx < 128 * 16; idx += 256) {
            int rr = idx >> 4, c8 = (idx & 15) * 8;
            *(float4*)(sWh + rr * PITCH + c8) = gWh[idx];
            *(float4*)(sWl + rr * PITCH + c8) = gWl[idx];
        }
    }
    __syncthreads();

    // stage C: k = ds @ Wk + bk -> fp16
    mainloop2(acc, aOff, bOffH, bOffL);
#pragma unroll
    for (int mi = 0; mi < 2; mi++) {
#pragma unroll
        for (int half = 0; half < 2; half++) {
            int grow = (int)tile * 128 + m0 + mi * 16 + half * 8 + r;
            if (grow >= Nreal) continue;
#pragma unroll
            for (int ni = 0; ni < 8; ni++) {
                int col = n0w + ni * 8 + c2;
                float o0 = acc[mi][ni][half * 2 + 0] + bk[col];
                float o1 = acc[mi][ni][half * 2 + 1] + bk[col + 1];
                *(__half2*)(g_kh + (size_t)grow * D + col) =
                    __halves2half2(__float2half_rn(o0), __float2half_rn(o1));
            }
        }
    }
}

// ---------------- counting sort of edges by src ----------------
__global__ void hist_kernel(const int* __restrict__ src, int E) {
    int e = blockIdx.x * blockDim.x + threadIdx.x;
    if (e < E) atomicAdd(&g_hist[src[e]], 1);
}

__global__ void scan_part_kernel(int n) {
    __shared__ int wsum[16];
    int b = blockIdx.x, t = threadIdx.x;
    int i = b * 512 + t;
    int v = (i < n) ? g_hist[i] : 0;
    int x = v;
#pragma unroll
    for (int d = 16; d; d >>= 1) x += __shfl_xor_sync(0xffffffffu, x, d);
    if ((t & 31) == 0) wsum[t >> 5] = x;
    __syncthreads();
    if (t < 16) {
        int s = wsum[t];
#pragma unroll
        for (int d = 8; d; d >>= 1) s += __shfl_xor_sync(0xffffu, s, d);
        if (t == 0) g_part[b] = s;
    }
}

__global__ void scan_mid_kernel(int nb) {
    __shared__ int wsum[4];
    int t = threadIdx.x, lane = t & 31, w = t >> 5;
    int v = (t < nb) ? g_part[t] : 0;
    int x = v;
#pragma unroll
    for (int d = 1; d < 32; d <<= 1) {
        int nbv = __shfl_up_sync(0xffffffffu, x, d);
        if (lane >= d) x += nbv;
    }
    if (lane == 31) wsum[w] = x;
    __syncthreads();
    if (t == 0) {
        int c = 0;
        for (int j = 0; j < 4; j++) { int tmp = wsum[j]; wsum[j] = c; c += tmp; }
    }
    __syncthreads();
    if (t < nb) g_part[t] = x - v + wsum[w];
}

__global__ void scan_final_kernel(int n, int E) {
    __shared__ int wsum[16];
    int b = blockIdx.x, t = threadIdx.x, lane = t & 31, w = t >> 5;
    int i = b * 512 + t;
    int v = (i < n) ? g_hist[i] : 0;
    int x = v;
#pragma unroll
    for (int d = 1; d < 32; d <<= 1) {
        int nbv = __shfl_up_sync(0xffffffffu, x, d);
        if (lane >= d) x += nbv;
    }
    if (lane == 31) wsum[w] = x;
    __syncthreads();
    if (t < 16) {
        int s = wsum[t];
#pragma unroll
        for (int d = 1; d < 16; d <<= 1) {
            int nbv = __shfl_up_sync(0xffffu, s, d);
            if ((t & 15) >= d) s += nbv;
        }
        wsum[t] = s;
    }
    __syncthreads();
    int base = g_part[b] + (w ? wsum[w - 1] : 0);
    if (i < n) {
        int excl = base + x - v;
        g_off[i] = excl;
        g_cur[i] = excl;
    }
    if (b == 0 && t == 0) g_off[n] = E;
}

__global__ void scatter_kernel(const int* __restrict__ src, const int* __restrict__ dst,
                               const float* __restrict__ w, int E) {
    int e = blockIdx.x * blockDim.x + threadIdx.x;
    if (e < E) {
        int s = src[e];
        int p = atomicAdd(&g_cur[s], 1);
        g_sdst[p] = dst[e];
        g_sw[p]   = w[e];
    }
}

// ---------------- aggregation: warp per src node, fp16 k/v, 4-edge unroll ----------------
__device__ __forceinline__ void edge_term(int dstn, float wgt, const float4& q,
                                          int lane, float4& acc) {
    uint2 kr = *(const uint2*)&g_kh[(size_t)dstn * D + lane * 4];
    float2 k01 = __half22float2(*(__half2*)&kr.x);
    float2 k23 = __half22float2(*(__half2*)&kr.y);
    float p = q.x * k01.x + q.y * k01.y + q.z * k23.x + q.w * k23.y;
    p += __shfl_xor_sync(0xffffffffu, p, 1);
    p += __shfl_xor_sync(0xffffffffu, p, 2);     // per-head (16-dim) dot
    float attn = wgt / (1.0f + expf(-p));
    uint2 vr = *(const uint2*)&g_vh[(size_t)dstn * D + lane * 4];
    float2 v01 = __half22float2(*(__half2*)&vr.x);
    float2 v23 = __half22float2(*(__half2*)&vr.y);
    acc.x += attn * v01.x;
    acc.y += attn * v01.y;
    acc.z += attn * v23.x;
    acc.w += attn * v23.y;
}

__global__ void agg_kernel(int n) {
    int warp = (blockIdx.x * blockDim.x + threadIdx.x) >> 5;
    int lane = threadIdx.x & 31;
    if (warp >= n) return;
    int beg = g_off[warp], end = g_off[warp + 1];
    float4 q = *(const float4*)&g_q[(size_t)warp * D + lane * 4];
    float4 acc = make_float4(0.f, 0.f, 0.f, 0.f);
    int e = beg;
    // 4-edge unroll: front-batch 4 dst/w, then 4 k-rows, then 4 v-rows (max MLP)
    for (; e + 3 < end; e += 4) {
        int dn[4];
        float wn[4];
#pragma unroll
        for (int j = 0; j < 4; j++) { dn[j] = g_sdst[e + j]; wn[j] = g_sw[e + j]; }
        uint2 kr[4], vr[4];
#pragma unroll
        for (int j = 0; j < 4; j++) kr[j] = *(const uint2*)&g_kh[(size_t)dn[j] * D + lane * 4];
#pragma unroll
        for (int j = 0; j < 4; j++) vr[j] = *(const uint2*)&g_vh[(size_t)dn[j] * D + lane * 4];
        float pp[4];
#pragma unroll
        for (int j = 0; j < 4; j++) {
            float2 ka = __half22float2(*(__half2*)&kr[j].x);
            float2 kb = __half22float2(*(__half2*)&kr[j].y);
            pp[j] = q.x * ka.x + q.y * ka.y + q.z * kb.x + q.w * kb.y;
        }
#pragma unroll
        for (int j = 0; j < 4; j++) {
            pp[j] += __shfl_xor_sync(0xffffffffu, pp[j], 1);
            pp[j] += __shfl_xor_sync(0xffffffffu, pp[j], 2);
        }
#pragma unroll
        for (int j = 0; j < 4; j++) {
            float a = wn[j] / (1.0f + expf(-pp[j]));
            float2 va = __half22float2(*(__half2*)&vr[j].x);
            float2 vb = __half22float2(*(__half2*)&vr[j].y);
            acc.x += a * va.x;
            acc.y += a * va.y;
            acc.z += a * vb.x;
            acc.w += a * vb.y;
        }
    }
    for (; e < end; e++) edge_term(g_sdst[e], g_sw[e], q, lane, acc);
    size_t base = (size_t)warp * D + lane * 4;
    *(__half2*)(g_agh + base)     = __halves2half2(__float2half_rn(acc.x), __float2half_rn(acc.y));
    *(__half2*)(g_agh + base + 2) = __halves2half2(__float2half_rn(acc.z), __float2half_rn(acc.w));
}

// ---------------- launch ----------------
extern "C" void kernel_launch(void* const* d_in, const int* in_sizes, int n_in,
                              void* d_out, int out_size) {
    const float* in_feats = (const float*)d_in[0];
    const float* struc    = (const float*)d_in[1];
    const float* ew       = (const float*)d_in[2];
    const float* ln_s     = (const float*)d_in[3];
    const float* ln_b     = (const float*)d_in[4];
    const float* Ws = (const float*)d_in[5];
    const float* bs = (const float*)d_in[6];
    const float* Wq = (const float*)d_in[7];
    const float* bq = (const float*)d_in[8];
    const float* Wk = (const float*)d_in[9];
    const float* bk = (const float*)d_in[10];
    const float* Wv = (const float*)d_in[11];
    const float* bv = (const float*)d_in[12];
    const float* Wo = (const float*)d_in[13];
    const int* eids = (const int*)d_in[14];

    int E = in_sizes[2];
    int N = in_sizes[0] / D;
    int tiles = (N + 127) / 128;
    int npad = tiles * 128;
    const int* src = eids;
    const int* dst = eids + E;

    static cudaStream_t s1 = nullptr, s2 = nullptr;
    static cudaEvent_t e_root = nullptr, e_prep = nullptr, e_w = nullptr,
                       e_v = nullptr, e_edges = nullptr;
    if (!s1) {
        cudaStreamCreateWithFlags(&s1, cudaStreamNonBlocking);
        cudaStreamCreateWithFlags(&s2, cudaStreamNonBlocking);
        cudaEventCreateWithFlags(&e_root,  cudaEventDisableTiming);
        cudaEventCreateWithFlags(&e_prep,  cudaEventDisableTiming);
        cudaEventCreateWithFlags(&e_w,     cudaEventDisableTiming);
        cudaEventCreateWithFlags(&e_v,     cudaEventDisableTiming);
        cudaEventCreateWithFlags(&e_edges, cudaEventDisableTiming);
        cudaFuncSetAttribute((const void*)mma_gemm,
                             cudaFuncAttributeMaxDynamicSharedMemorySize, SMEM_SZ);
        cudaFuncSetAttribute((const void*)mma_fused_dsqk,
                             cudaFuncAttributeMaxDynamicSharedMemorySize, SMEM_SZ);
    }

    float* p_q;
    __half *p_kh, *p_vh, *p_dh, *p_agh;
    int* p_hist;
    cudaGetSymbolAddress((void**)&p_q, g_q);
    cudaGetSymbolAddress((void**)&p_kh, g_kh);
    cudaGetSymbolAddress((void**)&p_vh, g_vh);
    cudaGetSymbolAddress((void**)&p_dh, g_dh);
    cudaGetSymbolAddress((void**)&p_agh, g_agh);
    cudaGetSymbolAddress((void**)&p_hist, g_hist);

    cudaEventRecord(e_root, 0);

    // branch s2: weight split (tiny) then edge counting sort
    cudaStreamWaitEvent(s2, e_root, 0);
    conv_w_kernel<<<5, 256, 0, s2>>>(Ws, Wq, Wk, Wv, Wo);
    cudaEventRecord(e_w, s2);
    int nb = (N + 511) / 512;
    cudaMemsetAsync(p_hist, 0, N * sizeof(int), s2);
    hist_kernel<<<(E + 255) / 256, 256, 0, s2>>>(src, E);
    scan_part_kernel<<<nb, 512, 0, s2>>>(N);
    scan_mid_kernel<<<1, 128, 0, s2>>>(nb);
    scan_final_kernel<<<nb, 512, 0, s2>>>(N, E);
    scatter_kernel<<<(E + 255) / 256, 256, 0, s2>>>(src, dst, ew, E);
    cudaEventRecord(e_edges, s2);

    // main stream: node prep
    ln_gelu_kernel<<<npad / 8, 256>>>(in_feats, struc, ln_s, ln_b, N, npad);
    cudaEventRecord(e_prep, 0);

    // branch s1: v = delta @ Wv^T + bv -> fp16 (overlaps fused dsqk)
    cudaStreamWaitEvent(s1, e_prep, 0);
    cudaStreamWaitEvent(s1, e_w, 0);
    mma_gemm<<<tiles, 256, SMEM_SZ, s1>>>(p_dh, 3, bv, nullptr, nullptr, p_vh, N, 1.0f);
    cudaEventRecord(e_v, s1);

    // main stream: fused ds -> q, k(fp16)
    cudaStreamWaitEvent(0, e_w, 0);
    mma_fused_dsqk<<<tiles, 256, SMEM_SZ>>>(bs, bq, bk, N);

    // join branches, aggregate, output
    cudaStreamWaitEvent(0, e_v, 0);
    cudaStreamWaitEvent(0, e_edges, 0);
    agg_kernel<<<(N * 32 + 255) / 256, 256>>>(N);
    mma_gemm<<<tiles, 256, SMEM_SZ>>>(p_agh, 4, nullptr, in_feats,
                                      (float*)d_out, nullptr, N, 1.0f);
}

// round 16
// speedup vs baseline: 1.6561x; 1.0394x over previous
#include <cuda_runtime.h>
#include <cuda_fp16.h>
#include <math.h>
#include <stdint.h>

#define NN 50000
#define NE 800000
#define D 128
#define NTILES_MAX 391
#define NP (NTILES_MAX * 128)
#define PITCH 136                      // fp16 elems per smem row (conflict-free ldmatrix)
#define SMEM_SZ (3 * 128 * PITCH * 2)  // 3 tiles: A, Wh, Wl  (102 KB)

// ---------------- scratch (no allocation allowed) ----------------
__device__ float g_q[NP * D];
__device__ __half g_kh[NP * D];                   // k (fp16)
__device__ __half g_vh[NP * D];                   // v (fp16)
__device__ __half g_sh[NP * D];                   // struc hi
__device__ __half g_dh[NP * D], g_dl[NP * D];     // delta hi/lo (lo only for ds addend)
__device__ __half g_agh[NP * D];                  // agg hi (pads stay zero)
__device__ __half g_wh[5 * D * D], g_wl[5 * D * D];
__device__ int   g_hist[NN];
__device__ int   g_off[NN + 1];
__device__ int   g_cur[NN];
__device__ int   g_part[128];
__device__ int   g_sdst[NE];
__device__ float g_sw[NE];

// ---------------- helpers ----------------
__device__ __forceinline__ uint32_t smem_u32(const void* p) {
    uint32_t a;
    asm("{ .reg .u64 t; cvta.to.shared.u64 t, %1; cvt.u32.u64 %0, t; }" : "=r"(a) : "l"(p));
    return a;
}

#define LDM_X4(r0, r1, r2, r3, addr) \
    asm volatile("ldmatrix.sync.aligned.m8n8.x4.shared.b16 {%0,%1,%2,%3}, [%4];" \
                 : "=r"(r0), "=r"(r1), "=r"(r2), "=r"(r3) : "r"(addr))

#define MMA16816(d, a, b) \
    asm volatile("mma.sync.aligned.m16n8k16.row.col.f32.f16.f16.f32 " \
                 "{%0,%1,%2,%3}, {%4,%5,%6,%7}, {%8,%9}, {%0,%1,%2,%3};" \
                 : "+f"((d)[0]), "+f"((d)[1]), "+f"((d)[2]), "+f"((d)[3]) \
                 : "r"((a)[0]), "r"((a)[1]), "r"((a)[2]), "r"((a)[3]), \
                   "r"((b)[0]), "r"((b)[1]))

// split f32 pair -> fp16 hi/lo at even index
__device__ __forceinline__ void store_hl(__half* bh, __half* bl,
                                         size_t idx, float x, float y) {
    __half hx = __float2half_rn(x), hy = __float2half_rn(y);
    float lx = x - __half2float(hx), ly = y - __half2float(hy);
    *(__half2*)(bh + idx) = __halves2half2(hx, hy);
    *(__half2*)(bl + idx) = __halves2half2(__float2half_rn(lx), __float2half_rn(ly));
}

// hi/lo mainloop over K=128.
// TERMS=2: acc += A*Bh + A*Bl     TERMS=1: acc += A*Bh (weight hi only)
template <int TERMS>
__device__ __forceinline__ void mainloop_t(float acc[2][8][4],
                                           uint32_t aOff, uint32_t bOffH, uint32_t bOffL) {
    const uint32_t aStep = 16 * PITCH * 2;
#pragma unroll
    for (int mi = 0; mi < 2; mi++)
#pragma unroll
        for (int ni = 0; ni < 8; ni++)
#pragma unroll
            for (int j = 0; j < 4; j++) acc[mi][ni][j] = 0.f;

#pragma unroll 2
    for (int s = 0; s < 8; s++) {
        uint32_t ko = s * 32;
        uint32_t a[2][4], bh[8][2], bl[8][2];
        LDM_X4(a[0][0], a[0][1], a[0][2], a[0][3], aOff + ko);
        LDM_X4(a[1][0], a[1][1], a[1][2], a[1][3], aOff + aStep + ko);
#pragma unroll
        for (int nb = 0; nb < 4; nb++) {
            uint32_t t0, t1, t2, t3;
            LDM_X4(t0, t1, t2, t3, bOffH + nb * aStep + ko);
            bh[nb * 2][0] = t0; bh[nb * 2][1] = t1;
            bh[nb * 2 + 1][0] = t2; bh[nb * 2 + 1][1] = t3;
            if (TERMS == 2) {
                LDM_X4(t0, t1, t2, t3, bOffL + nb * aStep + ko);
                bl[nb * 2][0] = t0; bl[nb * 2][1] = t1;
                bl[nb * 2 + 1][0] = t2; bl[nb * 2 + 1][1] = t3;
            }
        }
#pragma unroll
        for (int mi = 0; mi < 2; mi++)
#pragma unroll
            for (int ni = 0; ni < 8; ni++) {
                MMA16816(acc[mi][ni], a[mi], bh[ni]);
                if (TERMS == 2) MMA16816(acc[mi][ni], a[mi], bl[ni]);
            }
    }
}

// ---------------- LayerNorm + exact GELU + emit (warp per row) ----------------
__device__ __forceinline__ float gelu_exact(float h) {
    return 0.5f * h * (1.0f + erff(h * 0.70710678118654752f));
}

__global__ void ln_gelu_kernel(const float* __restrict__ x,
                               const float* __restrict__ struc,
                               const float* __restrict__ sc,
                               const float* __restrict__ bi, int n, int npad) {
    int warp = threadIdx.x >> 5;
    int lane = threadIdx.x & 31;
    int row = blockIdx.x * 8 + warp;
    if (row >= npad) return;
    int c0 = lane * 4;
    size_t base = (size_t)row * D + c0;

    float4 o = make_float4(0.f, 0.f, 0.f, 0.f);
    float4 sv = make_float4(0.f, 0.f, 0.f, 0.f);
    if (row < n) {
        float4 v = *(const float4*)(x + base);
        sv = *(const float4*)(struc + base);
        float s  = v.x + v.y + v.z + v.w;
        float ss = v.x * v.x + v.y * v.y + v.z * v.z + v.w * v.w;
#pragma unroll
        for (int d = 16; d; d >>= 1) {
            s  += __shfl_xor_sync(0xffffffffu, s, d);
            ss += __shfl_xor_sync(0xffffffffu, ss, d);
        }
        float mean = s * (1.0f / D);
        float var  = ss * (1.0f / D) - mean * mean;
        float rstd = rsqrtf(var + 1e-5f);
        float4 scv = *(const float4*)(sc + c0);
        float4 biv = *(const float4*)(bi + c0);
        o.x = gelu_exact((v.x - mean) * rstd * scv.x + biv.x);
        o.y = gelu_exact((v.y - mean) * rstd * scv.y + biv.y);
        o.z = gelu_exact((v.z - mean) * rstd * scv.z + biv.z);
        o.w = gelu_exact((v.w - mean) * rstd * scv.w + biv.w);
    }
    store_hl(g_dh, g_dl, base,     o.x, o.y);
    store_hl(g_dh, g_dl, base + 2, o.z, o.w);
    *(__half2*)(g_sh + base)     = __halves2half2(__float2half_rn(sv.x), __float2half_rn(sv.y));
    *(__half2*)(g_sh + base + 2) = __halves2half2(__float2half_rn(sv.z), __float2half_rn(sv.w));
}

// ---------------- weight split (5 x 128x128) ----------------
__global__ void conv_w_kernel(const float* __restrict__ W0, const float* __restrict__ W1,
                              const float* __restrict__ W2, const float* __restrict__ W3,
                              const float* __restrict__ W4) {
    int widx = blockIdx.x;
    const float* W = widx == 0 ? W0 : widx == 1 ? W1 : widx == 2 ? W2 : widx == 3 ? W3 : W4;
    __half* bh = g_wh + (size_t)widx * D * D;
    __half* bl = g_wl + (size_t)widx * D * D;
    for (int p = threadIdx.x; p < D * D / 2; p += blockDim.x) {
        size_t i = (size_t)p * 2;
        store_hl(bh, bl, i, W[i], W[i + 1]);
    }
}

// ---------------- generic mma GEMM: CTA = 128m x 128n x 128k ----------------
template <int TERMS>
__global__ void __launch_bounds__(256) mma_gemm(
    const __half* __restrict__ Ah, int widx,
    const float* __restrict__ bias, const float* __restrict__ addend,
    float* __restrict__ outF, __half* __restrict__ outHalf, int Mreal, float alpha)
{
    extern __shared__ char smem_raw[];
    __half* sA  = (__half*)smem_raw;
    __half* sWh = sA + 128 * PITCH;
    __half* sWl = sWh + 128 * PITCH;
    int tid = threadIdx.x, wid = tid >> 5, lane = tid & 31;
    size_t tile = blockIdx.x;

    {
        const float4* gA  = (const float4*)(Ah + tile * 128 * D);
        const float4* gWh = (const float4*)(g_wh + (size_t)widx * D * D);
        const float4* gWl = (const float4*)(g_wl + (size_t)widx * D * D);
        for (int idx = tid; idx < 128 * 16; idx += 256) {
            int r = idx >> 4, c8 = (idx & 15) * 8;
            *(float4*)(sA  + r * PITCH + c8) = gA[idx];
            *(float4*)(sWh + r * PITCH + c8) = gWh[idx];
            if (TERMS == 2) *(float4*)(sWl + r * PITCH + c8) = gWl[idx];
        }
    }
    __syncthreads();

    int m0 = (wid & 3) * 32;
    int n0w = (wid >> 2) * 64;
    int aRow = ((lane >> 3) & 1) * 8 + (lane & 7);
    int aCol = (lane >> 4) * 8;
    uint32_t aOff = smem_u32(sA) + ((m0 + aRow) * PITCH + aCol) * 2;
    int bRow = (lane >> 4) * 8 + (lane & 7);
    int bCol = ((lane >> 3) & 1) * 8;
    uint32_t bOffH = smem_u32(sWh) + ((n0w + bRow) * PITCH + bCol) * 2;
    uint32_t bOffL = smem_u32(sWl) + ((n0w + bRow) * PITCH + bCol) * 2;

    float acc[2][8][4];
    mainloop_t<TERMS>(acc, aOff, bOffH, bOffL);

    int r = lane >> 2, c2 = (lane & 3) * 2;
#pragma unroll
    for (int mi = 0; mi < 2; mi++) {
#pragma unroll
        for (int half = 0; half < 2; half++) {
            int grow = (int)tile * 128 + m0 + mi * 16 + half * 8 + r;
            if (grow >= Mreal) continue;
#pragma unroll
            for (int ni = 0; ni < 8; ni++) {
                int col = n0w + ni * 8 + c2;
                float o0 = acc[mi][ni][half * 2 + 0];
                float o1 = acc[mi][ni][half * 2 + 1];
                if (bias) { o0 += bias[col]; o1 += bias[col + 1]; }
                o0 *= alpha; o1 *= alpha;
                size_t idx = (size_t)grow * D + col;
                if (addend) {
                    float2 ad = *(const float2*)(addend + idx);
                    o0 += ad.x; o1 += ad.y;
                }
                if (outF) *(float2*)(outF + idx) = make_float2(o0, o1);
                if (outHalf)
                    *(__half2*)(outHalf + idx) =
                        __halves2half2(__float2half_rn(o0), __float2half_rn(o1));
            }
        }
    }
}

// ---------------- fused ds + q + k: ds stays in smem ----------------
// ds (2-term) -> smem; q (1-term) -> g_q; k (1-term) -> g_kh
__global__ void __launch_bounds__(256) mma_fused_dsqk(
    const float* __restrict__ bs, const float* __restrict__ bq,
    const float* __restrict__ bk, int Nreal)
{
    extern __shared__ char smem_raw[];
    __half* sA  = (__half*)smem_raw;
    __half* sWh = sA + 128 * PITCH;
    __half* sWl = sWh + 128 * PITCH;
    int tid = threadIdx.x, wid = tid >> 5, lane = tid & 31;
    size_t tile = blockIdx.x;

    // stage A: load struc hi + Ws hi/lo
    {
        const float4* gA  = (const float4*)(g_sh + tile * 128 * D);
        const float4* gWh = (const float4*)(g_wh);
        const float4* gWl = (const float4*)(g_wl);
        for (int idx = tid; idx < 128 * 16; idx += 256) {
            int r = idx >> 4, c8 = (idx & 15) * 8;
            *(float4*)(sA  + r * PITCH + c8) = gA[idx];
            *(float4*)(sWh + r * PITCH + c8) = gWh[idx];
            *(float4*)(sWl + r * PITCH + c8) = gWl[idx];
        }
    }
    __syncthreads();

    int m0 = (wid & 3) * 32;
    int n0w = (wid >> 2) * 64;
    int aRow = ((lane >> 3) & 1) * 8 + (lane & 7);
    int aCol = (lane >> 4) * 8;
    uint32_t aOff = smem_u32(sA) + ((m0 + aRow) * PITCH + aCol) * 2;
    int bRow = (lane >> 4) * 8 + (lane & 7);
    int bCol = ((lane >> 3) & 1) * 8;
    uint32_t bOffH = smem_u32(sWh) + ((n0w + bRow) * PITCH + bCol) * 2;
    uint32_t bOffL = smem_u32(sWl) + ((n0w + bRow) * PITCH + bCol) * 2;

    float acc[2][8][4];
    mainloop_t<2>(acc, aOff, bOffH, bOffL);          // struc @ Ws (2-term)
    __syncthreads();

    // ds epilogue -> overwrite sA with ds (fp16); delta addend from dh+dl; reload Wq (hi)
    int r = lane >> 2, c2 = (lane & 3) * 2;
#pragma unroll
    for (int mi = 0; mi < 2; mi++) {
#pragma unroll
        for (int half = 0; half < 2; half++) {
            int lrow = m0 + mi * 16 + half * 8 + r;
            size_t grow = tile * 128 + lrow;
#pragma unroll
            for (int ni = 0; ni < 8; ni++) {
                int col = n0w + ni * 8 + c2;
                size_t idx = grow * D + col;
                float2 dh = __half22float2(*(const __half2*)(g_dh + idx));
                float2 dl = __half22float2(*(const __half2*)(g_dl + idx));
                float o0 = acc[mi][ni][half * 2 + 0] + bs[col] + dh.x + dl.x;
                float o1 = acc[mi][ni][half * 2 + 1] + bs[col + 1] + dh.y + dl.y;
                *(__half2*)(sA + (size_t)lrow * PITCH + col) =
                    __halves2half2(__float2half_rn(o0), __float2half_rn(o1));
            }
        }
    }
    {
        const float4* gWh = (const float4*)(g_wh + (size_t)1 * D * D);
        for (int idx = tid; idx < 128 * 16; idx += 256) {
            int rr = idx >> 4, c8 = (idx & 15) * 8;
            *(float4*)(sWh + rr * PITCH + c8) = gWh[idx];
        }
    }
    __syncthreads();

    // stage B: q = (ds @ Wq_hi + bq) * 0.25  (1-term)
    mainloop_t<1>(acc, aOff, bOffH, bOffL);
#pragma unroll
    for (int mi = 0; mi < 2; mi++) {
#pragma unroll
        for (int half = 0; half < 2; half++) {
            int grow = (int)tile * 128 + m0 + mi * 16 + half * 8 + r;
            if (grow >= Nreal) continue;
#pragma unroll
            for (int ni = 0; ni < 8; ni++) {
                int col = n0w + ni * 8 + c2;
                float o0 = (acc[mi][ni][half * 2 + 0] + bq[col]) * 0.25f;
                float o1 = (acc[mi][ni][half * 2 + 1] + bq[col + 1]) * 0.25f;
                *(float2*)(g_q + (size_t)grow * D + col) = make_float2(o0, o1);
            }
        }
    }
    __syncthreads();
    {
        const float4* gWh = (const float4*)(g_wh + (size_t)2 * D * D);
        for (int idx = tid; idx < 128 * 16; idx += 256) {
            int rr = idx >> 4, c8 = (idx & 15) * 8;
            *(float4*)(sWh + rr * PITCH + c8) = gWh[idx];
        }
    }
    __syncthreads();

    // stage C: k = ds @ Wk_hi + bk -> fp16  (1-term)
    mainloop_t<1>(acc, aOff, bOffH, bOffL);
#pragma unroll
    for (int mi = 0; mi < 2; mi++) {
#pragma unroll
        for (int half = 0; half < 2; half++) {
            int grow = (int)tile * 128 + m0 + mi * 16 + half * 8 + r;
            if (grow >= Nreal) continue;
#pragma unroll
            for (int ni = 0; ni < 8; ni++) {
                int col = n0w + ni * 8 + c2;
                float o0 = acc[mi][ni][half * 2 + 0] + bk[col];
                float o1 = acc[mi][ni][half * 2 + 1] + bk[col + 1];
                *(__half2*)(g_kh + (size_t)grow * D + col) =
                    __halves2half2(__float2half_rn(o0), __float2half_rn(o1));
            }
        }
    }
}

// ---------------- counting sort of edges by src ----------------
__global__ void hist_kernel(const int* __restrict__ src, int E) {
    int e = blockIdx.x * blockDim.x + threadIdx.x;
    if (e < E) atomicAdd(&g_hist[src[e]], 1);
}

__global__ void scan_part_kernel(int n) {
    __shared__ int wsum[16];
    int b = blockIdx.x, t = threadIdx.x;
    int i = b * 512 + t;
    int v = (i < n) ? g_hist[i] : 0;
    int x = v;
#pragma unroll
    for (int d = 16; d; d >>= 1) x += __shfl_xor_sync(0xffffffffu, x, d);
    if ((t & 31) == 0) wsum[t >> 5] = x;
    __syncthreads();
    if (t < 16) {
        int s = wsum[t];
#pragma unroll
        for (int d = 8; d; d >>= 1) s += __shfl_xor_sync(0xffffu, s, d);
        if (t == 0) g_part[b] = s;
    }
}

__global__ void scan_mid_kernel(int nb) {
    __shared__ int wsum[4];
    int t = threadIdx.x, lane = t & 31, w = t >> 5;
    int v = (t < nb) ? g_part[t] : 0;
    int x = v;
#pragma unroll
    for (int d = 1; d < 32; d <<= 1) {
        int nbv = __shfl_up_sync(0xffffffffu, x, d);
        if (lane >= d) x += nbv;
    }
    if (lane == 31) wsum[w] = x;
    __syncthreads();
    if (t == 0) {
        int c = 0;
        for (int j = 0; j < 4; j++) { int tmp = wsum[j]; wsum[j] = c; c += tmp; }
    }
    __syncthreads();
    if (t < nb) g_part[t] = x - v + wsum[w];
}

__global__ void scan_final_kernel(int n, int E) {
    __shared__ int wsum[16];
    int b = blockIdx.x, t = threadIdx.x, lane = t & 31, w = t >> 5;
    int i = b * 512 + t;
    int v = (i < n) ? g_hist[i] : 0;
    int x = v;
#pragma unroll
    for (int d = 1; d < 32; d <<= 1) {
        int nbv = __shfl_up_sync(0xffffffffu, x, d);
        if (lane >= d) x += nbv;
    }
    if (lane == 31) wsum[w] = x;
    __syncthreads();
    if (t < 16) {
        int s = wsum[t];
#pragma unroll
        for (int d = 1; d < 16; d <<= 1) {
            int nbv = __shfl_up_sync(0xffffu, s, d);
            if ((t & 15) >= d) s += nbv;
        }
        wsum[t] = s;
    }
    __syncthreads();
    int base = g_part[b] + (w ? wsum[w - 1] : 0);
    if (i < n) {
        int excl = base + x - v;
        g_off[i] = excl;
        g_cur[i] = excl;
    }
    if (b == 0 && t == 0) g_off[n] = E;
}

__global__ void scatter_kernel(const int* __restrict__ src, const int* __restrict__ dst,
                               const float* __restrict__ w, int E) {
    int e = blockIdx.x * blockDim.x + threadIdx.x;
    if (e < E) {
        int s = src[e];
        int p = atomicAdd(&g_cur[s], 1);
        g_sdst[p] = dst[e];
        g_sw[p]   = w[e];
    }
}

// ---------------- aggregation: warp per src node, fp16 k/v, 2-edge unroll ----------------
__device__ __forceinline__ void edge_term(int dstn, float wgt, const float4& q,
                                          int lane, float4& acc) {
    uint2 kr = *(const uint2*)&g_kh[(size_t)dstn * D + lane * 4];
    float2 k01 = __half22float2(*(__half2*)&kr.x);
    float2 k23 = __half22float2(*(__half2*)&kr.y);
    float p = q.x * k01.x + q.y * k01.y + q.z * k23.x + q.w * k23.y;
    p += __shfl_xor_sync(0xffffffffu, p, 1);
    p += __shfl_xor_sync(0xffffffffu, p, 2);     // per-head (16-dim) dot
    float attn = wgt / (1.0f + expf(-p));
    uint2 vr = *(const uint2*)&g_vh[(size_t)dstn * D + lane * 4];
    float2 v01 = __half22float2(*(__half2*)&vr.x);
    float2 v23 = __half22float2(*(__half2*)&vr.y);
    acc.x += attn * v01.x;
    acc.y += attn * v01.y;
    acc.z += attn * v23.x;
    acc.w += attn * v23.y;
}

__global__ void agg_kernel(int n) {
    int warp = (blockIdx.x * blockDim.x + threadIdx.x) >> 5;
    int lane = threadIdx.x & 31;
    if (warp >= n) return;
    int beg = g_off[warp], end = g_off[warp + 1];
    float4 q = *(const float4*)&g_q[(size_t)warp * D + lane * 4];
    float4 acc = make_float4(0.f, 0.f, 0.f, 0.f);
    int e = beg;
    for (; e + 1 < end; e += 2) {
        int d0 = g_sdst[e], d1 = g_sdst[e + 1];
        float w0 = g_sw[e], w1 = g_sw[e + 1];
        uint2 kr0 = *(const uint2*)&g_kh[(size_t)d0 * D + lane * 4];
        uint2 kr1 = *(const uint2*)&g_kh[(size_t)d1 * D + lane * 4];
        uint2 vr0 = *(const uint2*)&g_vh[(size_t)d0 * D + lane * 4];
        uint2 vr1 = *(const uint2*)&g_vh[(size_t)d1 * D + lane * 4];
        float2 ka = __half22float2(*(__half2*)&kr0.x), kb = __half22float2(*(__half2*)&kr0.y);
        float2 kc = __half22float2(*(__half2*)&kr1.x), kd = __half22float2(*(__half2*)&kr1.y);
        float p0 = q.x * ka.x + q.y * ka.y + q.z * kb.x + q.w * kb.y;
        float p1 = q.x * kc.x + q.y * kc.y + q.z * kd.x + q.w * kd.y;
        p0 += __shfl_xor_sync(0xffffffffu, p0, 1);
        p0 += __shfl_xor_sync(0xffffffffu, p0, 2);
        p1 += __shfl_xor_sync(0xffffffffu, p1, 1);
        p1 += __shfl_xor_sync(0xffffffffu, p1, 2);
        float a0 = w0 / (1.0f + expf(-p0));
        float a1 = w1 / (1.0f + expf(-p1));
        float2 va = __half22float2(*(__half2*)&vr0.x), vb = __half22float2(*(__half2*)&vr0.y);
        float2 vc = __half22float2(*(__half2*)&vr1.x), vd = __half22float2(*(__half2*)&vr1.y);
        acc.x += a0 * va.x + a1 * vc.x;
        acc.y += a0 * va.y + a1 * vc.y;
        acc.z += a0 * vb.x + a1 * vd.x;
        acc.w += a0 * vb.y + a1 * vd.y;
    }
    if (e < end) edge_term(g_sdst[e], g_sw[e], q, lane, acc);
    size_t base = (size_t)warp * D + lane * 4;
    *(__half2*)(g_agh + base)     = __halves2half2(__float2half_rn(acc.x), __float2half_rn(acc.y));
    *(__half2*)(g_agh + base + 2) = __halves2half2(__float2half_rn(acc.z), __float2half_rn(acc.w));
}

// ---------------- launch ----------------
extern "C" void kernel_launch(void* const* d_in, const int* in_sizes, int n_in,
                              void* d_out, int out_size) {
    const float* in_feats = (const float*)d_in[0];
    const float* struc    = (const float*)d_in[1];
    const float* ew       = (const float*)d_in[2];
    const float* ln_s     = (const float*)d_in[3];
    const float* ln_b     = (const float*)d_in[4];
    const float* Ws = (const float*)d_in[5];
    const float* bs = (const float*)d_in[6];
    const float* Wq = (const float*)d_in[7];
    const float* bq = (const float*)d_in[8];
    const float* Wk = (const float*)d_in[9];
    const float* bk = (const float*)d_in[10];
    const float* Wv = (const float*)d_in[11];
    const float* bv = (const float*)d_in[12];
    const float* Wo = (const float*)d_in[13];
    const int* eids = (const int*)d_in[14];

    int E = in_sizes[2];
    int N = in_sizes[0] / D;
    int tiles = (N + 127) / 128;
    int npad = tiles * 128;
    const int* src = eids;
    const int* dst = eids + E;

    static cudaStream_t s1 = nullptr, s2 = nullptr;
    static cudaEvent_t e_root = nullptr, e_prep = nullptr, e_w = nullptr,
                       e_v = nullptr, e_edges = nullptr;
    if (!s1) {
        cudaStreamCreateWithFlags(&s1, cudaStreamNonBlocking);
        cudaStreamCreateWithFlags(&s2, cudaStreamNonBlocking);
        cudaEventCreateWithFlags(&e_root,  cudaEventDisableTiming);
        cudaEventCreateWithFlags(&e_prep,  cudaEventDisableTiming);
        cudaEventCreateWithFlags(&e_w,     cudaEventDisableTiming);
        cudaEventCreateWithFlags(&e_v,     cudaEventDisableTiming);
        cudaEventCreateWithFlags(&e_edges, cudaEventDisableTiming);
        cudaFuncSetAttribute((const void*)mma_gemm<1>,
                             cudaFuncAttributeMaxDynamicSharedMemorySize, SMEM_SZ);
        cudaFuncSetAttribute((const void*)mma_gemm<2>,
                             cudaFuncAttributeMaxDynamicSharedMemorySize, SMEM_SZ);
        cudaFuncSetAttribute((const void*)mma_fused_dsqk,
                             cudaFuncAttributeMaxDynamicSharedMemorySize, SMEM_SZ);
    }

    float* p_q;
    __half *p_kh, *p_vh, *p_dh, *p_agh;
    int* p_hist;
    cudaGetSymbolAddress((void**)&p_q, g_q);
    cudaGetSymbolAddress((void**)&p_kh, g_kh);
    cudaGetSymbolAddress((void**)&p_vh, g_vh);
    cudaGetSymbolAddress((void**)&p_dh, g_dh);
    cudaGetSymbolAddress((void**)&p_agh, g_agh);
    cudaGetSymbolAddress((void**)&p_hist, g_hist);

    cudaEventRecord(e_root, 0);

    // branch s2: weight split (tiny) then edge counting sort
    cudaStreamWaitEvent(s2, e_root, 0);
    conv_w_kernel<<<5, 256, 0, s2>>>(Ws, Wq, Wk, Wv, Wo);
    cudaEventRecord(e_w, s2);
    int nb = (N + 511) / 512;
    cudaMemsetAsync(p_hist, 0, N * sizeof(int), s2);
    hist_kernel<<<(E + 255) / 256, 256, 0, s2>>>(src, E);
    scan_part_kernel<<<nb, 512, 0, s2>>>(N);
    scan_mid_kernel<<<1, 128, 0, s2>>>(nb);
    scan_final_kernel<<<nb, 512, 0, s2>>>(N, E);
    scatter_kernel<<<(E + 255) / 256, 256, 0, s2>>>(src, dst, ew, E);
    cudaEventRecord(e_edges, s2);

    // main stream: node prep
    ln_gelu_kernel<<<npad / 8, 256>>>(in_feats, struc, ln_s, ln_b, N, npad);
    cudaEventRecord(e_prep, 0);

    // branch s1: v = delta @ Wv_hi^T + bv -> fp16 (1-term, overlaps fused dsqk)
    cudaStreamWaitEvent(s1, e_prep, 0);
    cudaStreamWaitEvent(s1, e_w, 0);
    mma_gemm<1><<<tiles, 256, SMEM_SZ, s1>>>(p_dh, 3, bv, nullptr, nullptr, p_vh, N, 1.0f);
    cudaEventRecord(e_v, s1);

    // main stream: fused ds -> q, k(fp16)
    cudaStreamWaitEvent(0, e_w, 0);
    mma_fused_dsqk<<<tiles, 256, SMEM_SZ>>>(bs, bq, bk, N);

    // join branches, aggregate, output (out-GEMM stays 2-term)
    cudaStreamWaitEvent(0, e_v, 0);
    cudaStreamWaitEvent(0, e_edges, 0);
    agg_kernel<<<(N * 32 + 255) / 256, 256>>>(N);
    mma_gemm<2><<<tiles, 256, SMEM_SZ>>>(p_agh, 4, nullptr, in_feats,
                                         (float*)d_out, nullptr, N, 1.0f);
}

// round 17
// speedup vs baseline: 1.7327x; 1.0462x over previous
#include <cuda_runtime.h>
#include <cuda_fp16.h>
#include <math.h>
#include <stdint.h>

#define NN 50000
#define NE 800000
#define D 128
#define NTILES_MAX 391
#define NP (NTILES_MAX * 128)
#define PITCH 136                      // fp16 elems per smem row (conflict-free ldmatrix)
#define SMEM_SZ (3 * 128 * PITCH * 2)  // 3 tiles: A, Wh, Wl  (102 KB)

// ---------------- scratch (no allocation allowed) ----------------
__device__ float g_q[NP * D];
__device__ __half g_kh[NP * D];                   // k (fp16)
__device__ __half g_vh[NP * D];                   // v (fp16)
__device__ __half g_sh[NP * D];                   // struc hi
__device__ __half g_dh[NP * D], g_dl[NP * D];     // delta hi/lo (lo only for ds addend)
__device__ __half g_agh[NP * D];                  // agg hi (pads stay zero)
__device__ __half g_wh[5 * D * D], g_wl[5 * D * D];
__device__ int   g_hist[NN];
__device__ int   g_off[NN + 1];
__device__ int   g_cur[NN];
__device__ int   g_part[128];
__device__ int   g_sdst[NE];
__device__ float g_sw[NE];

// ---------------- helpers ----------------
__device__ __forceinline__ uint32_t smem_u32(const void* p) {
    uint32_t a;
    asm("{ .reg .u64 t; cvta.to.shared.u64 t, %1; cvt.u32.u64 %0, t; }" : "=r"(a) : "l"(p));
    return a;
}

#define LDM_X4(r0, r1, r2, r3, addr) \
    asm volatile("ldmatrix.sync.aligned.m8n8.x4.shared.b16 {%0,%1,%2,%3}, [%4];" \
                 : "=r"(r0), "=r"(r1), "=r"(r2), "=r"(r3) : "r"(addr))

#define MMA16816(d, a, b) \
    asm volatile("mma.sync.aligned.m16n8k16.row.col.f32.f16.f16.f32 " \
                 "{%0,%1,%2,%3}, {%4,%5,%6,%7}, {%8,%9}, {%0,%1,%2,%3};" \
                 : "+f"((d)[0]), "+f"((d)[1]), "+f"((d)[2]), "+f"((d)[3]) \
                 : "r"((a)[0]), "r"((a)[1]), "r"((a)[2]), "r"((a)[3]), \
                   "r"((b)[0]), "r"((b)[1]))

// split f32 pair -> fp16 hi/lo at even index
__device__ __forceinline__ void store_hl(__half* bh, __half* bl,
                                         size_t idx, float x, float y) {
    __half hx = __float2half_rn(x), hy = __float2half_rn(y);
    float lx = x - __half2float(hx), ly = y - __half2float(hy);
    *(__half2*)(bh + idx) = __halves2half2(hx, hy);
    *(__half2*)(bl + idx) = __halves2half2(__float2half_rn(lx), __float2half_rn(ly));
}

// hi/lo mainloop over K=128.
// TERMS=2: acc += A*Bh + A*Bl     TERMS=1: acc += A*Bh (weight hi only)
template <int TERMS>
__device__ __forceinline__ void mainloop_t(float acc[2][8][4],
                                           uint32_t aOff, uint32_t bOffH, uint32_t bOffL) {
    const uint32_t aStep = 16 * PITCH * 2;
#pragma unroll
    for (int mi = 0; mi < 2; mi++)
#pragma unroll
        for (int ni = 0; ni < 8; ni++)
#pragma unroll
            for (int j = 0; j < 4; j++) acc[mi][ni][j] = 0.f;

#pragma unroll 2
    for (int s = 0; s < 8; s++) {
        uint32_t ko = s * 32;
        uint32_t a[2][4], bh[8][2], bl[8][2];
        LDM_X4(a[0][0], a[0][1], a[0][2], a[0][3], aOff + ko);
        LDM_X4(a[1][0], a[1][1], a[1][2], a[1][3], aOff + aStep + ko);
#pragma unroll
        for (int nb = 0; nb < 4; nb++) {
            uint32_t t0, t1, t2, t3;
            LDM_X4(t0, t1, t2, t3, bOffH + nb * aStep + ko);
            bh[nb * 2][0] = t0; bh[nb * 2][1] = t1;
            bh[nb * 2 + 1][0] = t2; bh[nb * 2 + 1][1] = t3;
            if (TERMS == 2) {
                LDM_X4(t0, t1, t2, t3, bOffL + nb * aStep + ko);
                bl[nb * 2][0] = t0; bl[nb * 2][1] = t1;
                bl[nb * 2 + 1][0] = t2; bl[nb * 2 + 1][1] = t3;
            }
        }
#pragma unroll
        for (int mi = 0; mi < 2; mi++)
#pragma unroll
            for (int ni = 0; ni < 8; ni++) {
                MMA16816(acc[mi][ni], a[mi], bh[ni]);
                if (TERMS == 2) MMA16816(acc[mi][ni], a[mi], bl[ni]);
            }
    }
}

// ---------------- LayerNorm + exact GELU + emit (warp per row) ----------------
__device__ __forceinline__ float gelu_exact(float h) {
    return 0.5f * h * (1.0f + erff(h * 0.70710678118654752f));
}

__global__ void ln_gelu_kernel(const float* __restrict__ x,
                               const float* __restrict__ struc,
                               const float* __restrict__ sc,
                               const float* __restrict__ bi, int n, int npad) {
    int warp = threadIdx.x >> 5;
    int lane = threadIdx.x & 31;
    int row = blockIdx.x * 8 + warp;
    if (row >= npad) return;
    int c0 = lane * 4;
    size_t base = (size_t)row * D + c0;

    float4 o = make_float4(0.f, 0.f, 0.f, 0.f);
    float4 sv = make_float4(0.f, 0.f, 0.f, 0.f);
    if (row < n) {
        float4 v = *(const float4*)(x + base);
        sv = *(const float4*)(struc + base);
        float s  = v.x + v.y + v.z + v.w;
        float ss = v.x * v.x + v.y * v.y + v.z * v.z + v.w * v.w;
#pragma unroll
        for (int d = 16; d; d >>= 1) {
            s  += __shfl_xor_sync(0xffffffffu, s, d);
            ss += __shfl_xor_sync(0xffffffffu, ss, d);
        }
        float mean = s * (1.0f / D);
        float var  = ss * (1.0f / D) - mean * mean;
        float rstd = rsqrtf(var + 1e-5f);
        float4 scv = *(const float4*)(sc + c0);
        float4 biv = *(const float4*)(bi + c0);
        o.x = gelu_exact((v.x - mean) * rstd * scv.x + biv.x);
        o.y = gelu_exact((v.y - mean) * rstd * scv.y + biv.y);
        o.z = gelu_exact((v.z - mean) * rstd * scv.z + biv.z);
        o.w = gelu_exact((v.w - mean) * rstd * scv.w + biv.w);
    }
    store_hl(g_dh, g_dl, base,     o.x, o.y);
    store_hl(g_dh, g_dl, base + 2, o.z, o.w);
    *(__half2*)(g_sh + base)     = __halves2half2(__float2half_rn(sv.x), __float2half_rn(sv.y));
    *(__half2*)(g_sh + base + 2) = __halves2half2(__float2half_rn(sv.z), __float2half_rn(sv.w));
}

// ---------------- weight split (5 x 128x128) ----------------
__global__ void conv_w_kernel(const float* __restrict__ W0, const float* __restrict__ W1,
                              const float* __restrict__ W2, const float* __restrict__ W3,
                              const float* __restrict__ W4) {
    int widx = blockIdx.x;
    const float* W = widx == 0 ? W0 : widx == 1 ? W1 : widx == 2 ? W2 : widx == 3 ? W3 : W4;
    __half* bh = g_wh + (size_t)widx * D * D;
    __half* bl = g_wl + (size_t)widx * D * D;
    for (int p = threadIdx.x; p < D * D / 2; p += blockDim.x) {
        size_t i = (size_t)p * 2;
        store_hl(bh, bl, i, W[i], W[i + 1]);
    }
}

// ---------------- generic mma GEMM: CTA = 128m x 128n x 128k ----------------
template <int TERMS>
__global__ void __launch_bounds__(256) mma_gemm(
    const __half* __restrict__ Ah, int widx,
    const float* __restrict__ bias, const float* __restrict__ addend,
    float* __restrict__ outF, __half* __restrict__ outHalf, int Mreal, float alpha)
{
    extern __shared__ char smem_raw[];
    __half* sA  = (__half*)smem_raw;
    __half* sWh = sA + 128 * PITCH;
    __half* sWl = sWh + 128 * PITCH;
    int tid = threadIdx.x, wid = tid >> 5, lane = tid & 31;
    size_t tile = blockIdx.x;

    {
        const float4* gA  = (const float4*)(Ah + tile * 128 * D);
        const float4* gWh = (const float4*)(g_wh + (size_t)widx * D * D);
        const float4* gWl = (const float4*)(g_wl + (size_t)widx * D * D);
        for (int idx = tid; idx < 128 * 16; idx += 256) {
            int r = idx >> 4, c8 = (idx & 15) * 8;
            *(float4*)(sA  + r * PITCH + c8) = gA[idx];
            *(float4*)(sWh + r * PITCH + c8) = gWh[idx];
            if (TERMS == 2) *(float4*)(sWl + r * PITCH + c8) = gWl[idx];
        }
    }
    __syncthreads();

    int m0 = (wid & 3) * 32;
    int n0w = (wid >> 2) * 64;
    int aRow = ((lane >> 3) & 1) * 8 + (lane & 7);
    int aCol = (lane >> 4) * 8;
    uint32_t aOff = smem_u32(sA) + ((m0 + aRow) * PITCH + aCol) * 2;
    int bRow = (lane >> 4) * 8 + (lane & 7);
    int bCol = ((lane >> 3) & 1) * 8;
    uint32_t bOffH = smem_u32(sWh) + ((n0w + bRow) * PITCH + bCol) * 2;
    uint32_t bOffL = smem_u32(sWl) + ((n0w + bRow) * PITCH + bCol) * 2;

    float acc[2][8][4];
    mainloop_t<TERMS>(acc, aOff, bOffH, bOffL);

    int r = lane >> 2, c2 = (lane & 3) * 2;
#pragma unroll
    for (int mi = 0; mi < 2; mi++) {
#pragma unroll
        for (int half = 0; half < 2; half++) {
            int grow = (int)tile * 128 + m0 + mi * 16 + half * 8 + r;
            if (grow >= Mreal) continue;
#pragma unroll
            for (int ni = 0; ni < 8; ni++) {
                int col = n0w + ni * 8 + c2;
                float o0 = acc[mi][ni][half * 2 + 0];
                float o1 = acc[mi][ni][half * 2 + 1];
                if (bias) { o0 += bias[col]; o1 += bias[col + 1]; }
                o0 *= alpha; o1 *= alpha;
                size_t idx = (size_t)grow * D + col;
                if (addend) {
                    float2 ad = *(const float2*)(addend + idx);
                    o0 += ad.x; o1 += ad.y;
                }
                if (outF) *(float2*)(outF + idx) = make_float2(o0, o1);
                if (outHalf)
                    *(__half2*)(outHalf + idx) =
                        __halves2half2(__float2half_rn(o0), __float2half_rn(o1));
            }
        }
    }
}

// ---------------- fused ds + q + k: ds stays in smem ----------------
// ds (2-term) -> smem; then Wq_hi->sWh, Wk_hi->sWl in ONE load round;
// stages B and C run back-to-back with no intervening sync.
__global__ void __launch_bounds__(256) mma_fused_dsqk(
    const float* __restrict__ bs, const float* __restrict__ bq,
    const float* __restrict__ bk, int Nreal)
{
    extern __shared__ char smem_raw[];
    __half* sA  = (__half*)smem_raw;
    __half* sWh = sA + 128 * PITCH;
    __half* sWl = sWh + 128 * PITCH;
    int tid = threadIdx.x, wid = tid >> 5, lane = tid & 31;
    size_t tile = blockIdx.x;

    // stage A: load struc hi + Ws hi/lo
    {
        const float4* gA  = (const float4*)(g_sh + tile * 128 * D);
        const float4* gWh = (const float4*)(g_wh);
        const float4* gWl = (const float4*)(g_wl);
        for (int idx = tid; idx < 128 * 16; idx += 256) {
            int r = idx >> 4, c8 = (idx & 15) * 8;
            *(float4*)(sA  + r * PITCH + c8) = gA[idx];
            *(float4*)(sWh + r * PITCH + c8) = gWh[idx];
            *(float4*)(sWl + r * PITCH + c8) = gWl[idx];
        }
    }
    __syncthreads();

    int m0 = (wid & 3) * 32;
    int n0w = (wid >> 2) * 64;
    int aRow = ((lane >> 3) & 1) * 8 + (lane & 7);
    int aCol = (lane >> 4) * 8;
    uint32_t aOff = smem_u32(sA) + ((m0 + aRow) * PITCH + aCol) * 2;
    int bRow = (lane >> 4) * 8 + (lane & 7);
    int bCol = ((lane >> 3) & 1) * 8;
    uint32_t bOffH = smem_u32(sWh) + ((n0w + bRow) * PITCH + bCol) * 2;
    uint32_t bOffL = smem_u32(sWl) + ((n0w + bRow) * PITCH + bCol) * 2;

    float acc[2][8][4];
    mainloop_t<2>(acc, aOff, bOffH, bOffL);          // struc @ Ws (2-term)
    __syncthreads();

    // ds epilogue -> overwrite sA with ds (fp16); delta addend from dh+dl;
    // simultaneously load Wq_hi -> sWh and Wk_hi -> sWl
    int r = lane >> 2, c2 = (lane & 3) * 2;
#pragma unroll
    for (int mi = 0; mi < 2; mi++) {
#pragma unroll
        for (int half = 0; half < 2; half++) {
            int lrow = m0 + mi * 16 + half * 8 + r;
            size_t grow = tile * 128 + lrow;
#pragma unroll
            for (int ni = 0; ni < 8; ni++) {
                int col = n0w + ni * 8 + c2;
                size_t idx = grow * D + col;
                float2 dh = __half22float2(*(const __half2*)(g_dh + idx));
                float2 dl = __half22float2(*(const __half2*)(g_dl + idx));
                float o0 = acc[mi][ni][half * 2 + 0] + bs[col] + dh.x + dl.x;
                float o1 = acc[mi][ni][half * 2 + 1] + bs[col + 1] + dh.y + dl.y;
                *(__half2*)(sA + (size_t)lrow * PITCH + col) =
                    __halves2half2(__float2half_rn(o0), __float2half_rn(o1));
            }
        }
    }
    {
        const float4* gWq = (const float4*)(g_wh + (size_t)1 * D * D);
        const float4* gWk = (const float4*)(g_wh + (size_t)2 * D * D);
        for (int idx = tid; idx < 128 * 16; idx += 256) {
            int rr = idx >> 4, c8 = (idx & 15) * 8;
            *(float4*)(sWh + rr * PITCH + c8) = gWq[idx];
            *(float4*)(sWl + rr * PITCH + c8) = gWk[idx];
        }
    }
    __syncthreads();

    // stage B: q = (ds @ Wq_hi + bq) * 0.25  (1-term, sWh)
    mainloop_t<1>(acc, aOff, bOffH, bOffL);
#pragma unroll
    for (int mi = 0; mi < 2; mi++) {
#pragma unroll
        for (int half = 0; half < 2; half++) {
            int grow = (int)tile * 128 + m0 + mi * 16 + half * 8 + r;
            if (grow >= Nreal) continue;
#pragma unroll
            for (int ni = 0; ni < 8; ni++) {
                int col = n0w + ni * 8 + c2;
                float o0 = (acc[mi][ni][half * 2 + 0] + bq[col]) * 0.25f;
                float o1 = (acc[mi][ni][half * 2 + 1] + bq[col + 1]) * 0.25f;
                *(float2*)(g_q + (size_t)grow * D + col) = make_float2(o0, o1);
            }
        }
    }

    // stage C: k = ds @ Wk_hi + bk -> fp16  (1-term, sWl; no sync needed — reads only)
    mainloop_t<1>(acc, aOff, bOffL, bOffH);
#pragma unroll
    for (int mi = 0; mi < 2; mi++) {
#pragma unroll
        for (int half = 0; half < 2; half++) {
            int grow = (int)tile * 128 + m0 + mi * 16 + half * 8 + r;
            if (grow >= Nreal) continue;
#pragma unroll
            for (int ni = 0; ni < 8; ni++) {
                int col = n0w + ni * 8 + c2;
                float o0 = acc[mi][ni][half * 2 + 0] + bk[col];
                float o1 = acc[mi][ni][half * 2 + 1] + bk[col + 1];
                *(__half2*)(g_kh + (size_t)grow * D + col) =
                    __halves2half2(__float2half_rn(o0), __float2half_rn(o1));
            }
        }
    }
}

// ---------------- counting sort of edges by src ----------------
__global__ void hist_kernel(const int* __restrict__ src, int E) {
    int e = blockIdx.x * blockDim.x + threadIdx.x;
    if (e < E) atomicAdd(&g_hist[src[e]], 1);
}

__global__ void scan_part_kernel(int n) {
    __shared__ int wsum[16];
    int b = blockIdx.x, t = threadIdx.x;
    int i = b * 512 + t;
    int v = (i < n) ? g_hist[i] : 0;
    int x = v;
#pragma unroll
    for (int d = 16; d; d >>= 1) x += __shfl_xor_sync(0xffffffffu, x, d);
    if ((t & 31) == 0) wsum[t >> 5] = x;
    __syncthreads();
    if (t < 16) {
        int s = wsum[t];
#pragma unroll
        for (int d = 8; d; d >>= 1) s += __shfl_xor_sync(0xffffu, s, d);
        if (t == 0) g_part[b] = s;
    }
}

__global__ void scan_mid_kernel(int nb) {
    __shared__ int wsum[4];
    int t = threadIdx.x, lane = t & 31, w = t >> 5;
    int v = (t < nb) ? g_part[t] : 0;
    int x = v;
#pragma unroll
    for (int d = 1; d < 32; d <<= 1) {
        int nbv = __shfl_up_sync(0xffffffffu, x, d);
        if (lane >= d) x += nbv;
    }
    if (lane == 31) wsum[w] = x;
    __syncthreads();
    if (t == 0) {
        int c = 0;
        for (int j = 0; j < 4; j++) { int tmp = wsum[j]; wsum[j] = c; c += tmp; }
    }
    __syncthreads();
    if (t < nb) g_part[t] = x - v + wsum[w];
}

__global__ void scan_final_kernel(int n, int E) {
    __shared__ int wsum[16];
    int b = blockIdx.x, t = threadIdx.x, lane = t & 31, w = t >> 5;
    int i = b * 512 + t;
    int v = (i < n) ? g_hist[i] : 0;
    int x = v;
#pragma unroll
    for (int d = 1; d < 32; d <<= 1) {
        int nbv = __shfl_up_sync(0xffffffffu, x, d);
        if (lane >= d) x += nbv;
    }
    if (lane == 31) wsum[w] = x;
    __syncthreads();
    if (t < 16) {
        int s = wsum[t];
#pragma unroll
        for (int d = 1; d < 16; d <<= 1) {
            int nbv = __shfl_up_sync(0xffffu, s, d);
            if ((t & 15) >= d) s += nbv;
        }
        wsum[t] = s;
    }
    __syncthreads();
    int base = g_part[b] + (w ? wsum[w - 1] : 0);
    if (i < n) {
        int excl = base + x - v;
        g_off[i] = excl;
        g_cur[i] = excl;
    }
    if (b == 0 && t == 0) g_off[n] = E;
}

__global__ void scatter_kernel(const int* __restrict__ src, const int* __restrict__ dst,
                               const float* __restrict__ w, int E) {
    int e = blockIdx.x * blockDim.x + threadIdx.x;
    if (e < E) {
        int s = src[e];
        int p = atomicAdd(&g_cur[s], 1);
        g_sdst[p] = dst[e];
        g_sw[p]   = w[e];
    }
}

// ---------------- aggregation: warp per src node, fp16 k/v, 2-edge unroll ----------------
__device__ __forceinline__ void edge_term(int dstn, float wgt, const float4& q,
                                          int lane, float4& acc) {
    uint2 kr = *(const uint2*)&g_kh[(size_t)dstn * D + lane * 4];
    float2 k01 = __half22float2(*(__half2*)&kr.x);
    float2 k23 = __half22float2(*(__half2*)&kr.y);
    float p = q.x * k01.x + q.y * k01.y + q.z * k23.x + q.w * k23.y;
    p += __shfl_xor_sync(0xffffffffu, p, 1);
    p += __shfl_xor_sync(0xffffffffu, p, 2);     // per-head (16-dim) dot
    float attn = wgt / (1.0f + expf(-p));
    uint2 vr = *(const uint2*)&g_vh[(size_t)dstn * D + lane * 4];
    float2 v01 = __half22float2(*(__half2*)&vr.x);
    float2 v23 = __half22float2(*(__half2*)&vr.y);
    acc.x += attn * v01.x;
    acc.y += attn * v01.y;
    acc.z += attn * v23.x;
    acc.w += attn * v23.y;
}

__global__ void agg_kernel(int n) {
    int warp = (blockIdx.x * blockDim.x + threadIdx.x) >> 5;
    int lane = threadIdx.x & 31;
    if (warp >= n) return;
    int beg = g_off[warp], end = g_off[warp + 1];
    float4 q = *(const float4*)&g_q[(size_t)warp * D + lane * 4];
    float4 acc = make_float4(0.f, 0.f, 0.f, 0.f);
    int e = beg;
    for (; e + 1 < end; e += 2) {
        int d0 = g_sdst[e], d1 = g_sdst[e + 1];
        float w0 = g_sw[e], w1 = g_sw[e + 1];
        uint2 kr0 = *(const uint2*)&g_kh[(size_t)d0 * D + lane * 4];
        uint2 kr1 = *(const uint2*)&g_kh[(size_t)d1 * D + lane * 4];
        uint2 vr0 = *(const uint2*)&g_vh[(size_t)d0 * D + lane * 4];
        uint2 vr1 = *(const uint2*)&g_vh[(size_t)d1 * D + lane * 4];
        float2 ka = __half22float2(*(__half2*)&kr0.x), kb = __half22float2(*(__half2*)&kr0.y);
        float2 kc = __half22float2(*(__half2*)&kr1.x), kd = __half22float2(*(__half2*)&kr1.y);
        float p0 = q.x * ka.x + q.y * ka.y + q.z * kb.x + q.w * kb.y;
        float p1 = q.x * kc.x + q.y * kc.y + q.z * kd.x + q.w * kd.y;
        p0 += __shfl_xor_sync(0xffffffffu, p0, 1);
        p0 += __shfl_xor_sync(0xffffffffu, p0, 2);
        p1 += __shfl_xor_sync(0xffffffffu, p1, 1);
        p1 += __shfl_xor_sync(0xffffffffu, p1, 2);
        float a0 = w0 / (1.0f + expf(-p0));
        float a1 = w1 / (1.0f + expf(-p1));
        float2 va = __half22float2(*(__half2*)&vr0.x), vb = __half22float2(*(__half2*)&vr0.y);
        float2 vc = __half22float2(*(__half2*)&vr1.x), vd = __half22float2(*(__half2*)&vr1.y);
        acc.x += a0 * va.x + a1 * vc.x;
        acc.y += a0 * va.y + a1 * vc.y;
        acc.z += a0 * vb.x + a1 * vd.x;
        acc.w += a0 * vb.y + a1 * vd.y;
    }
    if (e < end) edge_term(g_sdst[e], g_sw[e], q, lane, acc);
    size_t base = (size_t)warp * D + lane * 4;
    *(__half2*)(g_agh + base)     = __halves2half2(__float2half_rn(acc.x), __float2half_rn(acc.y));
    *(__half2*)(g_agh + base + 2) = __halves2half2(__float2half_rn(acc.z), __float2half_rn(acc.w));
}

// ---------------- launch ----------------
extern "C" void kernel_launch(void* const* d_in, const int* in_sizes, int n_in,
                              void* d_out, int out_size) {
    const float* in_feats = (const float*)d_in[0];
    const float* struc    = (const float*)d_in[1];
    const float* ew       = (const float*)d_in[2];
    const float* ln_s     = (const float*)d_in[3];
    const float* ln_b     = (const float*)d_in[4];
    const float* Ws = (const float*)d_in[5];
    const float* bs = (const float*)d_in[6];
    const float* Wq = (const float*)d_in[7];
    const float* bq = (const float*)d_in[8];
    const float* Wk = (const float*)d_in[9];
    const float* bk = (const float*)d_in[10];
    const float* Wv = (const float*)d_in[11];
    const float* bv = (const float*)d_in[12];
    const float* Wo = (const float*)d_in[13];
    const int* eids = (const int*)d_in[14];

    int E = in_sizes[2];
    int N = in_sizes[0] / D;
    int tiles = (N + 127) / 128;
    int npad = tiles * 128;
    const int* src = eids;
    const int* dst = eids + E;

    static cudaStream_t s1 = nullptr, s2 = nullptr;
    static cudaEvent_t e_root = nullptr, e_prep = nullptr, e_w = nullptr,
                       e_v = nullptr, e_edges = nullptr;
    if (!s1) {
        cudaStreamCreateWithFlags(&s1, cudaStreamNonBlocking);
        cudaStreamCreateWithFlags(&s2, cudaStreamNonBlocking);
        cudaEventCreateWithFlags(&e_root,  cudaEventDisableTiming);
        cudaEventCreateWithFlags(&e_prep,  cudaEventDisableTiming);
        cudaEventCreateWithFlags(&e_w,     cudaEventDisableTiming);
        cudaEventCreateWithFlags(&e_v,     cudaEventDisableTiming);
        cudaEventCreateWithFlags(&e_edges, cudaEventDisableTiming);
        cudaFuncSetAttribute((const void*)mma_gemm<1>,
                             cudaFuncAttributeMaxDynamicSharedMemorySize, SMEM_SZ);
        cudaFuncSetAttribute((const void*)mma_gemm<2>,
                             cudaFuncAttributeMaxDynamicSharedMemorySize, SMEM_SZ);
        cudaFuncSetAttribute((const void*)mma_fused_dsqk,
                             cudaFuncAttributeMaxDynamicSharedMemorySize, SMEM_SZ);
    }

    float* p_q;
    __half *p_kh, *p_vh, *p_dh, *p_agh;
    int* p_hist;
    cudaGetSymbolAddress((void**)&p_q, g_q);
    cudaGetSymbolAddress((void**)&p_kh, g_kh);
    cudaGetSymbolAddress((void**)&p_vh, g_vh);
    cudaGetSymbolAddress((void**)&p_dh, g_dh);
    cudaGetSymbolAddress((void**)&p_agh, g_agh);
    cudaGetSymbolAddress((void**)&p_hist, g_hist);

    cudaEventRecord(e_root, 0);

    // branch s2: weight split (tiny) then edge counting sort
    cudaStreamWaitEvent(s2, e_root, 0);
    conv_w_kernel<<<5, 256, 0, s2>>>(Ws, Wq, Wk, Wv, Wo);
    cudaEventRecord(e_w, s2);
    int nb = (N + 511) / 512;
    cudaMemsetAsync(p_hist, 0, N * sizeof(int), s2);
    hist_kernel<<<(E + 255) / 256, 256, 0, s2>>>(src, E);
    scan_part_kernel<<<nb, 512, 0, s2>>>(N);
    scan_mid_kernel<<<1, 128, 0, s2>>>(nb);
    scan_final_kernel<<<nb, 512, 0, s2>>>(N, E);
    scatter_kernel<<<(E + 255) / 256, 256, 0, s2>>>(src, dst, ew, E);
    cudaEventRecord(e_edges, s2);

    // main stream: node prep
    ln_gelu_kernel<<<npad / 8, 256>>>(in_feats, struc, ln_s, ln_b, N, npad);
    cudaEventRecord(e_prep, 0);

    // branch s1: v = delta @ Wv_hi^T + bv -> fp16 (1-term, overlaps fused dsqk)
    cudaStreamWaitEvent(s1, e_prep, 0);
    cudaStreamWaitEvent(s1, e_w, 0);
    mma_gemm<1><<<tiles, 256, SMEM_SZ, s1>>>(p_dh, 3, bv, nullptr, nullptr, p_vh, N, 1.0f);
    cudaEventRecord(e_v, s1);

    // main stream: fused ds -> q, k(fp16)
    cudaStreamWaitEvent(0, e_w, 0);
    mma_fused_dsqk<<<tiles, 256, SMEM_SZ>>>(bs, bq, bk, N);

    // join branches, aggregate, output (out-GEMM 1-term, Wo_hi)
    cudaStreamWaitEvent(0, e_v, 0);
    cudaStreamWaitEvent(0, e_edges, 0);
    agg_kernel<<<(N * 32 + 255) / 256, 256>>>(N);
    mma_gemm<1><<<tiles, 256, SMEM_SZ>>>(p_agh, 4, nullptr, in_feats,
                                         (float*)d_out, nullptr, N, 1.0f);
}